// round 1
// baseline (speedup 1.0000x reference)
#include <cuda_runtime.h>
#include <math.h>

// ---------------------------------------------------------------------------
// Problem constants
// ---------------------------------------------------------------------------
#define NB    8192      // batch
#define HID   1024
#define HEADS 8
#define ENCK  544       // 4*128 + 32
#define DECK  96
#define SDIM  512       // s columns
#define ADIM  128       // a columns
#define ACTN  32

// ---------------------------------------------------------------------------
// Scratch (device globals -- no runtime allocation allowed)
// ---------------------------------------------------------------------------
__device__ float g_xenc [NB * ENCK];            // concat(s, a[:, :32])
__device__ float g_enc  [NB * HID];             // enc_input
__device__ float g_dec  [NB * HID];             // dec_input
__device__ float g_h    [NB * HID];             // encoder_h (relu)
__device__ float g_dH   [NB * HID];             // decoder_H (relu)
__device__ float g_heads[HEADS * NB * HID];     // encoder_heads (relu)
__device__ float g_attn [NB * HEADS];           // softmax weights
__device__ float g_ctx  [NB * HID];             // context
__device__ float g_x    [NB * HID];             // relu(context@W1+b1)

// ---------------------------------------------------------------------------
// Concat kernel: g_xenc[b, 0:512] = s[b], g_xenc[b, 512:544] = a[b, 0:32]
// ---------------------------------------------------------------------------
__global__ void concat_kernel(const float* __restrict__ s,
                              const float* __restrict__ a)
{
    int idx = blockIdx.x * blockDim.x + threadIdx.x;
    if (idx >= NB * ENCK) return;
    int b = idx / ENCK;
    int c = idx - b * ENCK;
    g_xenc[idx] = (c < SDIM) ? s[(size_t)b * SDIM + c]
                             : a[(size_t)b * ADIM + (c - SDIM)];
}

// ---------------------------------------------------------------------------
// Classic 128x128x8 SGEMM, 256 threads, 8x8 per-thread micro-tile.
//   C[M,N] = act(A[M,K](row-major, lda) @ W[K,N](row-major) + bias)
// Requirements (all satisfied here): K%8==0, M%128==0, N%128==0,
// lda%4==0, all base pointers 16B aligned.
// blockIdx.z selects a (W, bias, C) slice via strides (for the 8 head GEMMs).
// ---------------------------------------------------------------------------
template <bool RELU>
__global__ __launch_bounds__(256)
void sgemm128(const float* __restrict__ A, int lda,
              const float* __restrict__ W, size_t wstride,
              const float* __restrict__ bias, size_t bstride,
              float* __restrict__ C, size_t cstride,
              int N, int K)
{
    __shared__ float As[8][128];
    __shared__ float Bs[8][128];

    const int tid = threadIdx.x;
    const int tx  = tid & 15;        // 0..15  (N direction)
    const int ty  = tid >> 4;        // 0..15  (M direction)
    const int bm  = blockIdx.y * 128;
    const int bn  = blockIdx.x * 128;
    const int z   = blockIdx.z;

    W    += (size_t)z * wstride;
    bias += (size_t)z * bstride;
    C    += (size_t)z * cstride;

    // A-tile loader: 128 rows x 8 cols; each thread one float4.
    const int arow = tid >> 1;            // 0..127
    const int acol = (tid & 1) * 4;       // 0 or 4
    // B-tile loader: 8 rows x 128 cols; each thread one float4.
    const int brow = tid >> 5;            // 0..7
    const int bcol = (tid & 31) * 4;      // 0..124

    const float* Aptr = A + (size_t)(bm + arow) * lda + acol;
    const float* Wptr = W + (size_t)brow * N + bn + bcol;

    float acc[8][8];
#pragma unroll
    for (int i = 0; i < 8; ++i)
#pragma unroll
        for (int j = 0; j < 8; ++j) acc[i][j] = 0.f;

    for (int k0 = 0; k0 < K; k0 += 8) {
        float4 av = *(const float4*)(Aptr + k0);
        As[acol + 0][arow] = av.x;
        As[acol + 1][arow] = av.y;
        As[acol + 2][arow] = av.z;
        As[acol + 3][arow] = av.w;
        *(float4*)&Bs[brow][bcol] = *(const float4*)(Wptr + (size_t)k0 * N);
        __syncthreads();

#pragma unroll
        for (int kk = 0; kk < 8; ++kk) {
            float af[8], bf[8];
            float4 a0 = *(const float4*)&As[kk][ty * 8];
            float4 a1 = *(const float4*)&As[kk][ty * 8 + 4];
            float4 b0 = *(const float4*)&Bs[kk][tx * 8];
            float4 b1 = *(const float4*)&Bs[kk][tx * 8 + 4];
            af[0]=a0.x; af[1]=a0.y; af[2]=a0.z; af[3]=a0.w;
            af[4]=a1.x; af[5]=a1.y; af[6]=a1.z; af[7]=a1.w;
            bf[0]=b0.x; bf[1]=b0.y; bf[2]=b0.z; bf[3]=b0.w;
            bf[4]=b1.x; bf[5]=b1.y; bf[6]=b1.z; bf[7]=b1.w;
#pragma unroll
            for (int i = 0; i < 8; ++i)
#pragma unroll
                for (int j = 0; j < 8; ++j)
                    acc[i][j] += af[i] * bf[j];
        }
        __syncthreads();
    }

    // Epilogue: bias + optional relu, float4 stores.
#pragma unroll
    for (int i = 0; i < 8; ++i) {
        size_t row = (size_t)(bm + ty * 8 + i);
        float* Crow = C + row * N + bn + tx * 8;
        const float* brow_ = bias + bn + tx * 8;
#pragma unroll
        for (int j = 0; j < 8; j += 4) {
            float4 v;
            v.x = acc[i][j + 0] + brow_[j + 0];
            v.y = acc[i][j + 1] + brow_[j + 1];
            v.z = acc[i][j + 2] + brow_[j + 2];
            v.w = acc[i][j + 3] + brow_[j + 3];
            if (RELU) {
                v.x = fmaxf(v.x, 0.f); v.y = fmaxf(v.y, 0.f);
                v.z = fmaxf(v.z, 0.f); v.w = fmaxf(v.w, 0.f);
            }
            *(float4*)(Crow + j) = v;
        }
    }
}

// ---------------------------------------------------------------------------
// scores[b,h] = dot(g_heads[h,b,:], g_dH[b,:]); softmax over h -> g_attn
// One block (256 thr = 8 warps) per batch row; warp w handles head w.
// ---------------------------------------------------------------------------
__global__ void scores_softmax_kernel()
{
    const int b    = blockIdx.x;
    const int w    = threadIdx.x >> 5;
    const int lane = threadIdx.x & 31;

    const float4* dH = (const float4*)(g_dH + (size_t)b * HID);
    const float4* eh = (const float4*)(g_heads + (size_t)w * NB * HID
                                               + (size_t)b * HID);
    float s = 0.f;
#pragma unroll 4
    for (int i = lane; i < HID / 4; i += 32) {
        float4 x = eh[i];
        float4 y = dH[i];
        s += x.x * y.x + x.y * y.y + x.z * y.z + x.w * y.w;
    }
#pragma unroll
    for (int o = 16; o > 0; o >>= 1) s += __shfl_xor_sync(0xffffffffu, s, o);

    __shared__ float sc[HEADS];
    if (lane == 0) sc[w] = s;
    __syncthreads();

    if (threadIdx.x == 0) {
        float m = sc[0];
#pragma unroll
        for (int h = 1; h < HEADS; ++h) m = fmaxf(m, sc[h]);
        float e[HEADS], sum = 0.f;
#pragma unroll
        for (int h = 0; h < HEADS; ++h) { e[h] = __expf(sc[h] - m); sum += e[h]; }
        float inv = 1.f / sum;
#pragma unroll
        for (int h = 0; h < HEADS; ++h) g_attn[(size_t)b * HEADS + h] = e[h] * inv;
    }
}

// ---------------------------------------------------------------------------
// context[b,d] = sum_h g_heads[h,b,d] * attn[b,h]   (float4-vectorized)
// ---------------------------------------------------------------------------
__global__ void context_kernel()
{
    int idx = blockIdx.x * blockDim.x + threadIdx.x;   // over NB*HID/4
    if (idx >= NB * HID / 4) return;
    int b = idx / (HID / 4);

    float w[HEADS];
#pragma unroll
    for (int h = 0; h < HEADS; ++h) w[h] = g_attn[(size_t)b * HEADS + h];

    float4 acc = make_float4(0.f, 0.f, 0.f, 0.f);
#pragma unroll
    for (int h = 0; h < HEADS; ++h) {
        float4 v = ((const float4*)g_heads)[(size_t)h * (NB * HID / 4) + idx];
        acc.x += v.x * w[h]; acc.y += v.y * w[h];
        acc.z += v.z * w[h]; acc.w += v.w * w[h];
    }
    ((float4*)g_ctx)[idx] = acc;
}

// ---------------------------------------------------------------------------
// q[b] = dot(g_x[b,:], W2) + b2   -- one warp per row
// ---------------------------------------------------------------------------
__global__ void final_dot_kernel(const float* __restrict__ W2,
                                 const float* __restrict__ b2,
                                 float* __restrict__ out)
{
    const int warp = (blockIdx.x * blockDim.x + threadIdx.x) >> 5;
    const int lane = threadIdx.x & 31;
    if (warp >= NB) return;

    const float4* xr = (const float4*)(g_x + (size_t)warp * HID);
    const float4* w4 = (const float4*)W2;
    float s = 0.f;
#pragma unroll 4
    for (int i = lane; i < HID / 4; i += 32) {
        float4 x = xr[i];
        float4 w = w4[i];
        s += x.x * w.x + x.y * w.y + x.z * w.z + x.w * w.w;
    }
#pragma unroll
    for (int o = 16; o > 0; o >>= 1) s += __shfl_xor_sync(0xffffffffu, s, o);
    if (lane == 0) out[warp] = s + b2[0];
}

// ---------------------------------------------------------------------------
// Launch
// ---------------------------------------------------------------------------
extern "C" void kernel_launch(void* const* d_in, const int* in_sizes, int n_in,
                              void* d_out, int out_size)
{
    const float* s        = (const float*)d_in[0];
    const float* a        = (const float*)d_in[1];
    const float* W_enc_in = (const float*)d_in[2];
    const float* b_enc_in = (const float*)d_in[3];
    const float* W_dec_in = (const float*)d_in[4];
    const float* b_dec_in = (const float*)d_in[5];
    const float* W_eh     = (const float*)d_in[6];
    const float* b_eh     = (const float*)d_in[7];
    const float* W_heads  = (const float*)d_in[8];
    const float* b_heads  = (const float*)d_in[9];
    const float* W_dh     = (const float*)d_in[10];
    const float* b_dh     = (const float*)d_in[11];
    const float* W1       = (const float*)d_in[12];
    const float* b1       = (const float*)d_in[13];
    const float* W2       = (const float*)d_in[14];
    const float* b2       = (const float*)d_in[15];
    float* out = (float*)d_out;

    float *xenc, *enc, *dec, *h, *dH, *heads, *ctx, *x;
    cudaGetSymbolAddress((void**)&xenc,  g_xenc);
    cudaGetSymbolAddress((void**)&enc,   g_enc);
    cudaGetSymbolAddress((void**)&dec,   g_dec);
    cudaGetSymbolAddress((void**)&h,     g_h);
    cudaGetSymbolAddress((void**)&dH,    g_dH);
    cudaGetSymbolAddress((void**)&heads, g_heads);
    cudaGetSymbolAddress((void**)&ctx,   g_ctx);
    cudaGetSymbolAddress((void**)&x,     g_x);

    const dim3 gemm_grid(HID / 128, NB / 128, 1);       // 8 x 64
    const dim3 head_grid(HID / 128, NB / 128, HEADS);   // 8 x 64 x 8

    // 1. concat(s, a[:, :32])
    concat_kernel<<<(NB * ENCK + 255) / 256, 256>>>(s, a);

    // 2. enc_input = xenc @ W_enc_in + b_enc_in
    sgemm128<false><<<gemm_grid, 256>>>(xenc, ENCK, W_enc_in, 0, b_enc_in, 0,
                                        enc, 0, HID, ENCK);
    // 3. dec_input = a[:, 32:] @ W_dec_in + b_dec_in
    sgemm128<false><<<gemm_grid, 256>>>(a + ACTN, ADIM, W_dec_in, 0, b_dec_in, 0,
                                        dec, 0, HID, DECK);
    // 4. encoder_h = relu(enc_input @ W_eh + b_eh)
    sgemm128<true><<<gemm_grid, 256>>>(enc, HID, W_eh, 0, b_eh, 0,
                                       h, 0, HID, HID);
    // 5. decoder_H = relu(dec_input @ W_dh + b_dh)
    sgemm128<true><<<gemm_grid, 256>>>(dec, HID, W_dh, 0, b_dh, 0,
                                       dH, 0, HID, HID);
    // 6. encoder_heads[h] = relu(encoder_h @ W_heads[h] + b_heads[h])
    sgemm128<true><<<head_grid, 256>>>(h, HID,
                                       W_heads, (size_t)HID * HID,
                                       b_heads, (size_t)HID,
                                       heads, (size_t)NB * HID,
                                       HID, HID);
    // 7. scores + softmax
    scores_softmax_kernel<<<NB, 256>>>();
    // 8. context
    context_kernel<<<(NB * HID / 4 + 255) / 256, 256>>>();
    // 9. x = relu(context @ W1 + b1)
    sgemm128<true><<<gemm_grid, 256>>>(ctx, HID, W1, 0, b1, 0,
                                       x, 0, HID, HID);
    // 10. q = x @ W2 + b2
    final_dot_kernel<<<NB / 8, 256>>>(W2, b2, out);
}

// round 2
// speedup vs baseline: 3.3257x; 3.3257x over previous
#include <cuda_runtime.h>
#include <math.h>
#include <stdint.h>

// ---------------------------------------------------------------------------
// Problem constants
// ---------------------------------------------------------------------------
#define NB    8192      // batch
#define HID   1024
#define HEADS 8
#define ENCK  544       // 4*128 + 32
#define DECK  96
#define SDIM  512       // s columns
#define ADIM  128       // a columns
#define ACTN  32

// ---------------------------------------------------------------------------
// Scratch (device globals -- no runtime allocation allowed)
// ---------------------------------------------------------------------------
__device__ float g_xenc [NB * ENCK];            // tf32(concat(s, a[:, :32]))
__device__ float g_adec [NB * DECK];            // tf32(a[:, 32:])
__device__ float g_enc  [NB * HID];             // enc_input (tf32-rounded)
__device__ float g_dec  [NB * HID];             // dec_input (tf32-rounded)
__device__ float g_h    [NB * HID];             // encoder_h (relu, tf32-rounded)
__device__ float g_dH   [NB * HID];             // decoder_H (relu, fp32)
__device__ float g_heads[HEADS * NB * HID];     // encoder_heads (relu, fp32)
__device__ float g_attn [NB * HEADS];           // softmax weights
__device__ float g_ctx  [NB * HID];             // context (tf32-rounded)
__device__ float g_x    [NB * HID];             // relu(context@W1+b1)

// tf32-rounded weight copies
__device__ float g_Wenc  [ENCK * HID];
__device__ float g_Wdec  [DECK * HID];
__device__ float g_Weh   [HID * HID];
__device__ float g_Wheads[HEADS * HID * HID];
__device__ float g_Wdh   [HID * HID];
__device__ float g_W1    [HID * HID];

// ---------------------------------------------------------------------------
// Helpers
// ---------------------------------------------------------------------------
__device__ __forceinline__ float tf32r(float f) {
    uint32_t u;
    asm("cvt.rna.tf32.f32 %0, %1;" : "=r"(u) : "f"(f));
    return __uint_as_float(u);
}

#define CP_ASYNC16(dst_u32, src_ptr) \
    asm volatile("cp.async.cg.shared.global [%0], [%1], 16;" \
                 :: "r"(dst_u32), "l"(src_ptr))
#define CP_COMMIT() asm volatile("cp.async.commit_group;")
#define CP_WAIT1()  asm volatile("cp.async.wait_group 1;")
#define CP_WAIT0()  asm volatile("cp.async.wait_group 0;")

// ---------------------------------------------------------------------------
// Elementwise fp32 -> tf32-rounded copy (float4)
// ---------------------------------------------------------------------------
__global__ void cvt_tf32_kernel(const float4* __restrict__ src,
                                float4* __restrict__ dst, int n4)
{
    int i = blockIdx.x * blockDim.x + threadIdx.x;
    if (i >= n4) return;
    float4 v = src[i];
    v.x = tf32r(v.x); v.y = tf32r(v.y); v.z = tf32r(v.z); v.w = tf32r(v.w);
    dst[i] = v;
}

// ---------------------------------------------------------------------------
// Concat + tf32-round inputs:
//   g_xenc[b,0:512]=s[b], g_xenc[b,512:544]=a[b,0:32];  g_adec[b,:]=a[b,32:128]
// ---------------------------------------------------------------------------
__global__ void concat_kernel(const float* __restrict__ s,
                              const float* __restrict__ a)
{
    int idx = blockIdx.x * blockDim.x + threadIdx.x;
    if (idx < NB * ENCK) {
        int b = idx / ENCK;
        int c = idx - b * ENCK;
        float v = (c < SDIM) ? s[(size_t)b * SDIM + c]
                             : a[(size_t)b * ADIM + (c - SDIM)];
        g_xenc[idx] = tf32r(v);
    } else {
        int j = idx - NB * ENCK;
        if (j >= NB * DECK) return;
        int b = j / DECK;
        int c = j - b * DECK;
        g_adec[j] = tf32r(a[(size_t)b * ADIM + ACTN + c]);
    }
}

// ---------------------------------------------------------------------------
// TF32 tensor-core GEMM: C[M,N] = act(A[M,K] @ W[K,N] + bias)
// A, W already tf32-rounded. 128x128 block tile, BK=32, double-buffered
// cp.async, 8 warps each computing 64x32 via m16n8k8 mma.sync.
// blockIdx.z slices (W, bias, C) for the batched head GEMM.
// ---------------------------------------------------------------------------
#define AS_STRIDE 36     // floats per A smem row (pad 32->36: conflict-free LDSM)
#define BS_STRIDE 132    // floats per B smem row
#define AS_BUF    (128 * AS_STRIDE)   // 4608 floats
#define BS_BUF    (32 * BS_STRIDE)    // 4224 floats
#define SMEM_GEMM ((2 * AS_BUF + 2 * BS_BUF) * 4)  // 70656 bytes

template <bool RELU, bool CVTOUT>
__global__ __launch_bounds__(256, 2)
void tf32gemm(const float* __restrict__ A, int lda,
              const float* __restrict__ W, size_t wstride,
              const float* __restrict__ bias, size_t bstride,
              float* __restrict__ C, size_t cstride,
              int N, int K)
{
    extern __shared__ float smem[];
    float* Bs_f = smem + 2 * AS_BUF;

    const int tid    = threadIdx.x;
    const int lane   = tid & 31;
    const int wid    = tid >> 5;
    const int warp_m = wid >> 2;       // 0..1
    const int warp_n = wid & 3;        // 0..3
    const int bm = blockIdx.y * 128;
    const int bn = blockIdx.x * 128;
    const int z  = blockIdx.z;

    W    += (size_t)z * wstride;
    bias += (size_t)z * bstride;
    C    += (size_t)z * cstride;

    const uint32_t smem_u = (uint32_t)__cvta_generic_to_shared(smem);
    const uint32_t Bs_u   = smem_u + 2 * AS_BUF * 4;

    // ldmatrix lane geometry for A (16x8 tf32 tile per mma)
    const int lm_row = ((lane >> 3) & 1) * 8 + (lane & 7);  // + warp_m*64 + mt*16
    const int lm_col = ((lane >> 4) << 2);                  // + ks*8

    const float* Ag = A + (size_t)bm * lda;
    const float* Wg = W + bn;

    float acc[4][4][4];
#pragma unroll
    for (int mt = 0; mt < 4; ++mt)
#pragma unroll
        for (int nt = 0; nt < 4; ++nt)
#pragma unroll
            for (int r = 0; r < 4; ++r) acc[mt][nt][r] = 0.f;

    const int S = K >> 5;   // stages of 32

    // -- async tile loader -------------------------------------------------
    auto load_stage = [&](int s, int buf) {
        const int k0 = s << 5;
        const uint32_t abase = smem_u + (uint32_t)buf * AS_BUF * 4;
        const uint32_t bbase = Bs_u   + (uint32_t)buf * BS_BUF * 4;
#pragma unroll
        for (int j = 0; j < 4; ++j) {
            int i = tid + 256 * j;
            int r = i >> 3, c = (i & 7) << 2;                // A: 128 x 32
            CP_ASYNC16(abase + (uint32_t)(r * AS_STRIDE + c) * 4,
                       Ag + (size_t)r * lda + k0 + c);
        }
#pragma unroll
        for (int j = 0; j < 4; ++j) {
            int i = tid + 256 * j;
            int r = i >> 5, c = (i & 31) << 2;               // B: 32 x 128
            CP_ASYNC16(bbase + (uint32_t)(r * BS_STRIDE + c) * 4,
                       Wg + (size_t)(k0 + r) * N + c);
        }
        CP_COMMIT();
    };

    load_stage(0, 0);

    for (int s = 0; s < S; ++s) {
        const int buf = s & 1;
        if (s + 1 < S) { load_stage(s + 1, buf ^ 1); CP_WAIT1(); }
        else           { CP_WAIT0(); }
        __syncthreads();

        const uint32_t abase = smem_u + (uint32_t)buf * AS_BUF * 4;
        const float*   Bsb   = Bs_f + buf * BS_BUF;

#pragma unroll
        for (int ks = 0; ks < 4; ++ks) {
            uint32_t afr[4][4];
#pragma unroll
            for (int mt = 0; mt < 4; ++mt) {
                uint32_t addr = abase +
                    (uint32_t)(((warp_m * 64 + mt * 16 + lm_row) * AS_STRIDE)
                               + lm_col + ks * 8) * 4;
                asm volatile(
                    "ldmatrix.sync.aligned.m8n8.x4.shared.b16 "
                    "{%0,%1,%2,%3}, [%4];"
                    : "=r"(afr[mt][0]), "=r"(afr[mt][1]),
                      "=r"(afr[mt][2]), "=r"(afr[mt][3])
                    : "r"(addr));
            }
            uint32_t bfr[4][2];
#pragma unroll
            for (int nt = 0; nt < 4; ++nt) {
                int col = warp_n * 32 + nt * 8 + (lane >> 2);
                int row = ks * 8 + (lane & 3);
                bfr[nt][0] = __float_as_uint(Bsb[row * BS_STRIDE + col]);
                bfr[nt][1] = __float_as_uint(Bsb[(row + 4) * BS_STRIDE + col]);
            }
#pragma unroll
            for (int mt = 0; mt < 4; ++mt)
#pragma unroll
                for (int nt = 0; nt < 4; ++nt) {
                    asm volatile(
                        "mma.sync.aligned.m16n8k8.row.col.f32.tf32.tf32.f32 "
                        "{%0,%1,%2,%3},{%4,%5,%6,%7},{%8,%9},{%0,%1,%2,%3};"
                        : "+f"(acc[mt][nt][0]), "+f"(acc[mt][nt][1]),
                          "+f"(acc[mt][nt][2]), "+f"(acc[mt][nt][3])
                        : "r"(afr[mt][0]), "r"(afr[mt][1]),
                          "r"(afr[mt][2]), "r"(afr[mt][3]),
                          "r"(bfr[nt][0]), "r"(bfr[nt][1]));
                }
        }
        __syncthreads();
    }

    // -- epilogue: bias (+relu) (+tf32 round), float2 stores ---------------
#pragma unroll
    for (int mt = 0; mt < 4; ++mt) {
        const int row0 = bm + warp_m * 64 + mt * 16 + (lane >> 2);
#pragma unroll
        for (int nt = 0; nt < 4; ++nt) {
            const int col = bn + warp_n * 32 + nt * 8 + 2 * (lane & 3);
            const float2 bv = *(const float2*)(bias + col);
            float2 v0, v1;
            v0.x = acc[mt][nt][0] + bv.x;
            v0.y = acc[mt][nt][1] + bv.y;
            v1.x = acc[mt][nt][2] + bv.x;
            v1.y = acc[mt][nt][3] + bv.y;
            if (RELU) {
                v0.x = fmaxf(v0.x, 0.f); v0.y = fmaxf(v0.y, 0.f);
                v1.x = fmaxf(v1.x, 0.f); v1.y = fmaxf(v1.y, 0.f);
            }
            if (CVTOUT) {
                v0.x = tf32r(v0.x); v0.y = tf32r(v0.y);
                v1.x = tf32r(v1.x); v1.y = tf32r(v1.y);
            }
            *(float2*)(C + (size_t)row0 * N + col)       = v0;
            *(float2*)(C + (size_t)(row0 + 8) * N + col) = v1;
        }
    }
}

// ---------------------------------------------------------------------------
// scores[b,h] = dot(g_heads[h,b,:], g_dH[b,:]); softmax over h -> g_attn
// ---------------------------------------------------------------------------
__global__ void scores_softmax_kernel()
{
    const int b    = blockIdx.x;
    const int w    = threadIdx.x >> 5;
    const int lane = threadIdx.x & 31;

    const float4* dH = (const float4*)(g_dH + (size_t)b * HID);
    const float4* eh = (const float4*)(g_heads + (size_t)w * NB * HID
                                               + (size_t)b * HID);
    float s = 0.f;
#pragma unroll 4
    for (int i = lane; i < HID / 4; i += 32) {
        float4 x = eh[i];
        float4 y = dH[i];
        s += x.x * y.x + x.y * y.y + x.z * y.z + x.w * y.w;
    }
#pragma unroll
    for (int o = 16; o > 0; o >>= 1) s += __shfl_xor_sync(0xffffffffu, s, o);

    __shared__ float sc[HEADS];
    if (lane == 0) sc[w] = s;
    __syncthreads();

    if (threadIdx.x == 0) {
        float m = sc[0];
#pragma unroll
        for (int h = 1; h < HEADS; ++h) m = fmaxf(m, sc[h]);
        float e[HEADS], sum = 0.f;
#pragma unroll
        for (int h = 0; h < HEADS; ++h) { e[h] = __expf(sc[h] - m); sum += e[h]; }
        float inv = 1.f / sum;
#pragma unroll
        for (int h = 0; h < HEADS; ++h) g_attn[(size_t)b * HEADS + h] = e[h] * inv;
    }
}

// ---------------------------------------------------------------------------
// context[b,d] = sum_h g_heads[h,b,d] * attn[b,h]  (tf32-rounded output)
// ---------------------------------------------------------------------------
__global__ void context_kernel()
{
    int idx = blockIdx.x * blockDim.x + threadIdx.x;   // over NB*HID/4
    if (idx >= NB * HID / 4) return;
    int b = idx / (HID / 4);

    float w[HEADS];
#pragma unroll
    for (int h = 0; h < HEADS; ++h) w[h] = g_attn[(size_t)b * HEADS + h];

    float4 acc = make_float4(0.f, 0.f, 0.f, 0.f);
#pragma unroll
    for (int h = 0; h < HEADS; ++h) {
        float4 v = ((const float4*)g_heads)[(size_t)h * (NB * HID / 4) + idx];
        acc.x += v.x * w[h]; acc.y += v.y * w[h];
        acc.z += v.z * w[h]; acc.w += v.w * w[h];
    }
    acc.x = tf32r(acc.x); acc.y = tf32r(acc.y);
    acc.z = tf32r(acc.z); acc.w = tf32r(acc.w);
    ((float4*)g_ctx)[idx] = acc;
}

// ---------------------------------------------------------------------------
// q[b] = dot(g_x[b,:], W2) + b2   -- one warp per row (fp32)
// ---------------------------------------------------------------------------
__global__ void final_dot_kernel(const float* __restrict__ W2,
                                 const float* __restrict__ b2,
                                 float* __restrict__ out)
{
    const int warp = (blockIdx.x * blockDim.x + threadIdx.x) >> 5;
    const int lane = threadIdx.x & 31;
    if (warp >= NB) return;

    const float4* xr = (const float4*)(g_x + (size_t)warp * HID);
    const float4* w4 = (const float4*)W2;
    float s = 0.f;
#pragma unroll 4
    for (int i = lane; i < HID / 4; i += 32) {
        float4 x = xr[i];
        float4 w = w4[i];
        s += x.x * w.x + x.y * w.y + x.z * w.z + x.w * w.w;
    }
#pragma unroll
    for (int o = 16; o > 0; o >>= 1) s += __shfl_xor_sync(0xffffffffu, s, o);
    if (lane == 0) out[warp] = s + b2[0];
}

// ---------------------------------------------------------------------------
// Launch
// ---------------------------------------------------------------------------
extern "C" void kernel_launch(void* const* d_in, const int* in_sizes, int n_in,
                              void* d_out, int out_size)
{
    const float* s        = (const float*)d_in[0];
    const float* a        = (const float*)d_in[1];
    const float* W_enc_in = (const float*)d_in[2];
    const float* b_enc_in = (const float*)d_in[3];
    const float* W_dec_in = (const float*)d_in[4];
    const float* b_dec_in = (const float*)d_in[5];
    const float* W_eh     = (const float*)d_in[6];
    const float* b_eh     = (const float*)d_in[7];
    const float* W_heads  = (const float*)d_in[8];
    const float* b_heads  = (const float*)d_in[9];
    const float* W_dh     = (const float*)d_in[10];
    const float* b_dh     = (const float*)d_in[11];
    const float* W1       = (const float*)d_in[12];
    const float* b1       = (const float*)d_in[13];
    const float* W2       = (const float*)d_in[14];
    const float* b2       = (const float*)d_in[15];
    float* out = (float*)d_out;

    float *xenc, *adec, *enc, *dec, *h, *dH, *heads, *ctx, *x;
    float *wenc, *wdec, *weh, *wheads, *wdh, *w1c;
    cudaGetSymbolAddress((void**)&xenc,   g_xenc);
    cudaGetSymbolAddress((void**)&adec,   g_adec);
    cudaGetSymbolAddress((void**)&enc,    g_enc);
    cudaGetSymbolAddress((void**)&dec,    g_dec);
    cudaGetSymbolAddress((void**)&h,      g_h);
    cudaGetSymbolAddress((void**)&dH,     g_dH);
    cudaGetSymbolAddress((void**)&heads,  g_heads);
    cudaGetSymbolAddress((void**)&ctx,    g_ctx);
    cudaGetSymbolAddress((void**)&x,      g_x);
    cudaGetSymbolAddress((void**)&wenc,   g_Wenc);
    cudaGetSymbolAddress((void**)&wdec,   g_Wdec);
    cudaGetSymbolAddress((void**)&weh,    g_Weh);
    cudaGetSymbolAddress((void**)&wheads, g_Wheads);
    cudaGetSymbolAddress((void**)&wdh,    g_Wdh);
    cudaGetSymbolAddress((void**)&w1c,    g_W1);

    cudaFuncSetAttribute(tf32gemm<false, true>,
                         cudaFuncAttributeMaxDynamicSharedMemorySize, SMEM_GEMM);
    cudaFuncSetAttribute(tf32gemm<true, true>,
                         cudaFuncAttributeMaxDynamicSharedMemorySize, SMEM_GEMM);
    cudaFuncSetAttribute(tf32gemm<true, false>,
                         cudaFuncAttributeMaxDynamicSharedMemorySize, SMEM_GEMM);

    const dim3 gemm_grid(HID / 128, NB / 128, 1);       // 8 x 64
    const dim3 head_grid(HID / 128, NB / 128, HEADS);   // 8 x 64 x 8

    // 0. tf32-round weight copies
    cvt_tf32_kernel<<<(ENCK * HID / 4 + 255) / 256, 256>>>((const float4*)W_enc_in, (float4*)wenc,   ENCK * HID / 4);
    cvt_tf32_kernel<<<(DECK * HID / 4 + 255) / 256, 256>>>((const float4*)W_dec_in, (float4*)wdec,   DECK * HID / 4);
    cvt_tf32_kernel<<<(HID * HID / 4 + 255) / 256, 256>>>((const float4*)W_eh,      (float4*)weh,    HID * HID / 4);
    cvt_tf32_kernel<<<(HEADS * HID * HID / 4 + 255) / 256, 256>>>((const float4*)W_heads, (float4*)wheads, HEADS * HID * HID / 4);
    cvt_tf32_kernel<<<(HID * HID / 4 + 255) / 256, 256>>>((const float4*)W_dh,      (float4*)wdh,    HID * HID / 4);
    cvt_tf32_kernel<<<(HID * HID / 4 + 255) / 256, 256>>>((const float4*)W1,        (float4*)w1c,    HID * HID / 4);

    // 1. concat + round inputs
    concat_kernel<<<(NB * (ENCK + DECK) + 255) / 256, 256>>>(s, a);

    // 2. enc_input = xenc @ W_enc_in + b_enc_in            (rounded out)
    tf32gemm<false, true><<<gemm_grid, 256, SMEM_GEMM>>>(xenc, ENCK, wenc, 0, b_enc_in, 0, enc, 0, HID, ENCK);
    // 3. dec_input = adec @ W_dec_in + b_dec_in            (rounded out)
    tf32gemm<false, true><<<gemm_grid, 256, SMEM_GEMM>>>(adec, DECK, wdec, 0, b_dec_in, 0, dec, 0, HID, DECK);
    // 4. encoder_h = relu(enc @ W_eh + b_eh)               (rounded out)
    tf32gemm<true, true><<<gemm_grid, 256, SMEM_GEMM>>>(enc, HID, weh, 0, b_eh, 0, h, 0, HID, HID);
    // 5. decoder_H = relu(dec @ W_dh + b_dh)               (fp32 out)
    tf32gemm<true, false><<<gemm_grid, 256, SMEM_GEMM>>>(dec, HID, wdh, 0, b_dh, 0, dH, 0, HID, HID);
    // 6. encoder_heads[h] = relu(h @ W_heads[h] + b_heads[h])  (fp32 out)
    tf32gemm<true, false><<<head_grid, 256, SMEM_GEMM>>>(h, HID,
                                                         wheads, (size_t)HID * HID,
                                                         b_heads, (size_t)HID,
                                                         heads, (size_t)NB * HID,
                                                         HID, HID);
    // 7. scores + softmax
    scores_softmax_kernel<<<NB, 256>>>();
    // 8. context (tf32-rounded out)
    context_kernel<<<(NB * HID / 4 + 255) / 256, 256>>>();
    // 9. x = relu(ctx @ W1 + b1)                           (fp32 out)
    tf32gemm<true, false><<<gemm_grid, 256, SMEM_GEMM>>>(ctx, HID, w1c, 0, b1, 0, x, 0, HID, HID);
    // 10. q = x @ W2 + b2
    final_dot_kernel<<<NB / 8, 256>>>(W2, b2, out);
}

// round 3
// speedup vs baseline: 5.5869x; 1.6799x over previous
#include <cuda_runtime.h>
#include <cuda_fp16.h>
#include <math.h>
#include <stdint.h>

// ---------------------------------------------------------------------------
// Problem constants
// ---------------------------------------------------------------------------
#define NB    8192      // batch
#define HID   1024
#define HEADS 8
#define ENCK  544       // 4*128 + 32
#define DECK  96
#define SDIM  512       // s columns
#define ADIM  128       // a columns
#define ACTN  32

// ---------------------------------------------------------------------------
// Scratch (device globals -- no runtime allocation allowed)
// ---------------------------------------------------------------------------
__device__ __align__(256) __half g_xenc [NB * ENCK];   // fp16(concat(s, a[:,:32]))
__device__ __align__(256) __half g_adec [NB * DECK];   // fp16(a[:, 32:])
__device__ __align__(256) __half g_enc  [NB * HID];    // enc_input (fp16)
__device__ __align__(256) __half g_dec  [NB * HID];    // dec_input (fp16)
__device__ __align__(256) __half g_h    [NB * HID];    // encoder_h (relu, fp16)
__device__ __align__(256) float  g_dH   [NB * HID];    // decoder_H (relu, fp32)
__device__ __align__(256) float  g_heads[HEADS * NB * HID]; // encoder_heads fp32
__device__ __align__(256) float  g_attn [NB * HEADS];  // softmax weights
__device__ __align__(256) __half g_ctx  [NB * HID];    // context (fp16)
__device__ __align__(256) float  g_x    [NB * HID];    // relu(ctx@W1+b1) fp32

// fp16 weight copies
__device__ __align__(256) __half g_Wenc  [ENCK * HID];
__device__ __align__(256) __half g_Wdec  [DECK * HID];
__device__ __align__(256) __half g_Weh   [HID * HID];
__device__ __align__(256) __half g_Wheads[HEADS * HID * HID];
__device__ __align__(256) __half g_Wdh   [HID * HID];
__device__ __align__(256) __half g_W1    [HID * HID];

// ---------------------------------------------------------------------------
// Helpers
// ---------------------------------------------------------------------------
#define CP_ASYNC16(dst_u32, src_ptr) \
    asm volatile("cp.async.cg.shared.global [%0], [%1], 16;" \
                 :: "r"(dst_u32), "l"(src_ptr))
#define CP_COMMIT() asm volatile("cp.async.commit_group;")
#define CP_WAIT1()  asm volatile("cp.async.wait_group 1;")
#define CP_WAIT0()  asm volatile("cp.async.wait_group 0;")

// ---------------------------------------------------------------------------
// Elementwise fp32 -> fp16 copy (reads float4, writes 8B)
// ---------------------------------------------------------------------------
__global__ void cvt_fp16_kernel(const float4* __restrict__ src,
                                __half2* __restrict__ dst, int n4)
{
    int i = blockIdx.x * blockDim.x + threadIdx.x;
    if (i >= n4) return;
    float4 v = src[i];
    dst[2 * i]     = __floats2half2_rn(v.x, v.y);
    dst[2 * i + 1] = __floats2half2_rn(v.z, v.w);
}

// ---------------------------------------------------------------------------
// Concat + fp16 inputs
// ---------------------------------------------------------------------------
__global__ void concat_kernel(const float* __restrict__ s,
                              const float* __restrict__ a)
{
    int idx = blockIdx.x * blockDim.x + threadIdx.x;
    if (idx < NB * ENCK) {
        int b = idx / ENCK;
        int c = idx - b * ENCK;
        float v = (c < SDIM) ? s[(size_t)b * SDIM + c]
                             : a[(size_t)b * ADIM + (c - SDIM)];
        g_xenc[idx] = __float2half_rn(v);
    } else {
        int j = idx - NB * ENCK;
        if (j >= NB * DECK) return;
        int b = j / DECK;
        int c = j - b * DECK;
        g_adec[j] = __float2half_rn(a[(size_t)b * ADIM + ACTN + c]);
    }
}

// ---------------------------------------------------------------------------
// FP16 tensor-core GEMM: C[M,N] = act(A[M,K] @ W[K,N] + bias)
// 128x128 block tile, BK=32, double-buffered cp.async,
// 8 warps each computing 64x32 via m16n8k16 mma.sync.
// HALF_OUT selects fp16 vs fp32 output. blockIdx.z slices (W,bias,C).
// ---------------------------------------------------------------------------
#define AS_STRIDE 40     // halves per A smem row (32 + 8 pad)
#define BS_STRIDE 136    // halves per B smem row (128 + 8 pad)
#define AS_BUF    (128 * AS_STRIDE)   // 5120 halves
#define BS_BUF    (32 * BS_STRIDE)    // 4352 halves
#define SMEM_GEMM ((2 * AS_BUF + 2 * BS_BUF) * 2)  // 37888 bytes

template <bool RELU, bool HALF_OUT>
__global__ __launch_bounds__(256, 2)
void hgemm(const __half* __restrict__ A, int lda,
           const __half* __restrict__ W, size_t wstride,
           const float* __restrict__ bias, size_t bstride,
           void* __restrict__ Cv, size_t cstride,
           int N, int K)
{
    extern __shared__ __half smem[];

    const int tid    = threadIdx.x;
    const int lane   = tid & 31;
    const int wid    = tid >> 5;
    const int warp_m = wid >> 2;       // 0..1
    const int warp_n = wid & 3;        // 0..3
    const int bm = blockIdx.y * 128;
    const int bn = blockIdx.x * 128;
    const int z  = blockIdx.z;

    W    += (size_t)z * wstride;
    bias += (size_t)z * bstride;

    const uint32_t smem_u = (uint32_t)__cvta_generic_to_shared(smem);
    const uint32_t Bs_u   = smem_u + 2 * AS_BUF * 2;

    const __half* Ag = A + (size_t)bm * lda;
    const __half* Wg = W + bn;

    float acc[4][4][4];
#pragma unroll
    for (int mt = 0; mt < 4; ++mt)
#pragma unroll
        for (int nt = 0; nt < 4; ++nt)
#pragma unroll
            for (int r = 0; r < 4; ++r) acc[mt][nt][r] = 0.f;

    const int S = K >> 5;   // stages of 32

    auto load_stage = [&](int s, int buf) {
        const int k0 = s << 5;
        const uint32_t abase = smem_u + (uint32_t)buf * AS_BUF * 2;
        const uint32_t bbase = Bs_u   + (uint32_t)buf * BS_BUF * 2;
#pragma unroll
        for (int j = 0; j < 2; ++j) {                 // A: 128 x 32 halves
            int i = tid + 256 * j;
            int r = i >> 2, c = (i & 3) << 3;         // 4 chunks of 8h per row
            CP_ASYNC16(abase + (uint32_t)(r * AS_STRIDE + c) * 2,
                       Ag + (size_t)r * lda + k0 + c);
        }
#pragma unroll
        for (int j = 0; j < 2; ++j) {                 // B: 32 x 128 halves
            int i = tid + 256 * j;
            int r = i >> 4, c = (i & 15) << 3;        // 16 chunks per row
            CP_ASYNC16(bbase + (uint32_t)(r * BS_STRIDE + c) * 2,
                       Wg + (size_t)(k0 + r) * N + c);
        }
        CP_COMMIT();
    };

    load_stage(0, 0);

    // ldmatrix lane geometry
    const int a_row = lane & 15;              // + warp_m*64 + mt*16
    const int a_col = (lane >> 4) << 3;       // + ks*16
    const int b_row = lane & 15;              // + ks*16

    for (int s = 0; s < S; ++s) {
        const int buf = s & 1;
        if (s + 1 < S) { load_stage(s + 1, buf ^ 1); CP_WAIT1(); }
        else           { CP_WAIT0(); }
        __syncthreads();

        const uint32_t abase = smem_u + (uint32_t)buf * AS_BUF * 2;
        const uint32_t bbase = Bs_u   + (uint32_t)buf * BS_BUF * 2;

#pragma unroll
        for (int ks = 0; ks < 2; ++ks) {
            uint32_t afr[4][4];
#pragma unroll
            for (int mt = 0; mt < 4; ++mt) {
                uint32_t addr = abase +
                    (uint32_t)((warp_m * 64 + mt * 16 + a_row) * AS_STRIDE
                               + ks * 16 + a_col) * 2;
                asm volatile(
                    "ldmatrix.sync.aligned.m8n8.x4.shared.b16 "
                    "{%0,%1,%2,%3}, [%4];"
                    : "=r"(afr[mt][0]), "=r"(afr[mt][1]),
                      "=r"(afr[mt][2]), "=r"(afr[mt][3])
                    : "r"(addr));
            }
            uint32_t bfr[4][2];
#pragma unroll
            for (int nt = 0; nt < 4; ++nt) {
                uint32_t addr = bbase +
                    (uint32_t)((ks * 16 + b_row) * BS_STRIDE
                               + warp_n * 32 + nt * 8) * 2;
                asm volatile(
                    "ldmatrix.sync.aligned.m8n8.x2.trans.shared.b16 "
                    "{%0,%1}, [%2];"
                    : "=r"(bfr[nt][0]), "=r"(bfr[nt][1])
                    : "r"(addr));
            }
#pragma unroll
            for (int mt = 0; mt < 4; ++mt)
#pragma unroll
                for (int nt = 0; nt < 4; ++nt) {
                    asm volatile(
                        "mma.sync.aligned.m16n8k16.row.col.f32.f16.f16.f32 "
                        "{%0,%1,%2,%3},{%4,%5,%6,%7},{%8,%9},{%0,%1,%2,%3};"
                        : "+f"(acc[mt][nt][0]), "+f"(acc[mt][nt][1]),
                          "+f"(acc[mt][nt][2]), "+f"(acc[mt][nt][3])
                        : "r"(afr[mt][0]), "r"(afr[mt][1]),
                          "r"(afr[mt][2]), "r"(afr[mt][3]),
                          "r"(bfr[nt][0]), "r"(bfr[nt][1]));
                }
        }
        __syncthreads();
    }

    // -- epilogue ----------------------------------------------------------
#pragma unroll
    for (int mt = 0; mt < 4; ++mt) {
        const int row0 = bm + warp_m * 64 + mt * 16 + (lane >> 2);
#pragma unroll
        for (int nt = 0; nt < 4; ++nt) {
            const int col = bn + warp_n * 32 + nt * 8 + 2 * (lane & 3);
            const float2 bv = *(const float2*)(bias + col);
            float2 v0, v1;
            v0.x = acc[mt][nt][0] + bv.x;
            v0.y = acc[mt][nt][1] + bv.y;
            v1.x = acc[mt][nt][2] + bv.x;
            v1.y = acc[mt][nt][3] + bv.y;
            if (RELU) {
                v0.x = fmaxf(v0.x, 0.f); v0.y = fmaxf(v0.y, 0.f);
                v1.x = fmaxf(v1.x, 0.f); v1.y = fmaxf(v1.y, 0.f);
            }
            if (HALF_OUT) {
                __half* C = (__half*)Cv + (size_t)z * cstride;
                *(__half2*)(C + (size_t)row0 * N + col)       = __floats2half2_rn(v0.x, v0.y);
                *(__half2*)(C + (size_t)(row0 + 8) * N + col) = __floats2half2_rn(v1.x, v1.y);
            } else {
                float* C = (float*)Cv + (size_t)z * cstride;
                *(float2*)(C + (size_t)row0 * N + col)       = v0;
                *(float2*)(C + (size_t)(row0 + 8) * N + col) = v1;
            }
        }
    }
}

// ---------------------------------------------------------------------------
// scores[b,h] = dot(g_heads[h,b,:], g_dH[b,:]); softmax over h -> g_attn
// ---------------------------------------------------------------------------
__global__ void scores_softmax_kernel()
{
    const int b    = blockIdx.x;
    const int w    = threadIdx.x >> 5;
    const int lane = threadIdx.x & 31;

    const float4* dH = (const float4*)(g_dH + (size_t)b * HID);
    const float4* eh = (const float4*)(g_heads + (size_t)w * NB * HID
                                               + (size_t)b * HID);
    float s = 0.f;
#pragma unroll 4
    for (int i = lane; i < HID / 4; i += 32) {
        float4 x = eh[i];
        float4 y = dH[i];
        s += x.x * y.x + x.y * y.y + x.z * y.z + x.w * y.w;
    }
#pragma unroll
    for (int o = 16; o > 0; o >>= 1) s += __shfl_xor_sync(0xffffffffu, s, o);

    __shared__ float sc[HEADS];
    if (lane == 0) sc[w] = s;
    __syncthreads();

    if (threadIdx.x == 0) {
        float m = sc[0];
#pragma unroll
        for (int h = 1; h < HEADS; ++h) m = fmaxf(m, sc[h]);
        float e[HEADS], sum = 0.f;
#pragma unroll
        for (int h = 0; h < HEADS; ++h) { e[h] = __expf(sc[h] - m); sum += e[h]; }
        float inv = 1.f / sum;
#pragma unroll
        for (int h = 0; h < HEADS; ++h) g_attn[(size_t)b * HEADS + h] = e[h] * inv;
    }
}

// ---------------------------------------------------------------------------
// context[b,d] = sum_h g_heads[h,b,d] * attn[b,h]  -> fp16 g_ctx
// ---------------------------------------------------------------------------
__global__ void context_kernel()
{
    int idx = blockIdx.x * blockDim.x + threadIdx.x;   // over NB*HID/4
    if (idx >= NB * HID / 4) return;
    int b = idx / (HID / 4);

    float w[HEADS];
#pragma unroll
    for (int h = 0; h < HEADS; ++h) w[h] = g_attn[(size_t)b * HEADS + h];

    float4 acc = make_float4(0.f, 0.f, 0.f, 0.f);
#pragma unroll
    for (int h = 0; h < HEADS; ++h) {
        float4 v = ((const float4*)g_heads)[(size_t)h * (NB * HID / 4) + idx];
        acc.x += v.x * w[h]; acc.y += v.y * w[h];
        acc.z += v.z * w[h]; acc.w += v.w * w[h];
    }
    __half2* dst = (__half2*)g_ctx;
    dst[2 * idx]     = __floats2half2_rn(acc.x, acc.y);
    dst[2 * idx + 1] = __floats2half2_rn(acc.z, acc.w);
}

// ---------------------------------------------------------------------------
// q[b] = dot(g_x[b,:], W2) + b2   -- one warp per row (fp32)
// ---------------------------------------------------------------------------
__global__ void final_dot_kernel(const float* __restrict__ W2,
                                 const float* __restrict__ b2,
                                 float* __restrict__ out)
{
    const int warp = (blockIdx.x * blockDim.x + threadIdx.x) >> 5;
    const int lane = threadIdx.x & 31;
    if (warp >= NB) return;

    const float4* xr = (const float4*)(g_x + (size_t)warp * HID);
    const float4* w4 = (const float4*)W2;
    float s = 0.f;
#pragma unroll 4
    for (int i = lane; i < HID / 4; i += 32) {
        float4 x = xr[i];
        float4 w = w4[i];
        s += x.x * w.x + x.y * w.y + x.z * w.z + x.w * w.w;
    }
#pragma unroll
    for (int o = 16; o > 0; o >>= 1) s += __shfl_xor_sync(0xffffffffu, s, o);
    if (lane == 0) out[warp] = s + b2[0];
}

// ---------------------------------------------------------------------------
// Launch
// ---------------------------------------------------------------------------
extern "C" void kernel_launch(void* const* d_in, const int* in_sizes, int n_in,
                              void* d_out, int out_size)
{
    const float* s        = (const float*)d_in[0];
    const float* a        = (const float*)d_in[1];
    const float* W_enc_in = (const float*)d_in[2];
    const float* b_enc_in = (const float*)d_in[3];
    const float* W_dec_in = (const float*)d_in[4];
    const float* b_dec_in = (const float*)d_in[5];
    const float* W_eh     = (const float*)d_in[6];
    const float* b_eh     = (const float*)d_in[7];
    const float* W_heads  = (const float*)d_in[8];
    const float* b_heads  = (const float*)d_in[9];
    const float* W_dh     = (const float*)d_in[10];
    const float* b_dh     = (const float*)d_in[11];
    const float* W1       = (const float*)d_in[12];
    const float* b1       = (const float*)d_in[13];
    const float* W2       = (const float*)d_in[14];
    const float* b2       = (const float*)d_in[15];
    float* out = (float*)d_out;

    __half *xenc, *adec, *enc, *dec, *h, *ctx;
    float *dH, *heads, *x;
    __half *wenc, *wdec, *weh, *wheads, *wdh, *w1c;
    cudaGetSymbolAddress((void**)&xenc,   g_xenc);
    cudaGetSymbolAddress((void**)&adec,   g_adec);
    cudaGetSymbolAddress((void**)&enc,    g_enc);
    cudaGetSymbolAddress((void**)&dec,    g_dec);
    cudaGetSymbolAddress((void**)&h,      g_h);
    cudaGetSymbolAddress((void**)&dH,     g_dH);
    cudaGetSymbolAddress((void**)&heads,  g_heads);
    cudaGetSymbolAddress((void**)&ctx,    g_ctx);
    cudaGetSymbolAddress((void**)&x,      g_x);
    cudaGetSymbolAddress((void**)&wenc,   g_Wenc);
    cudaGetSymbolAddress((void**)&wdec,   g_Wdec);
    cudaGetSymbolAddress((void**)&weh,    g_Weh);
    cudaGetSymbolAddress((void**)&wheads, g_Wheads);
    cudaGetSymbolAddress((void**)&wdh,    g_Wdh);
    cudaGetSymbolAddress((void**)&w1c,    g_W1);

    cudaFuncSetAttribute(hgemm<false, true>,
                         cudaFuncAttributeMaxDynamicSharedMemorySize, SMEM_GEMM);
    cudaFuncSetAttribute(hgemm<true, true>,
                         cudaFuncAttributeMaxDynamicSharedMemorySize, SMEM_GEMM);
    cudaFuncSetAttribute(hgemm<true, false>,
                         cudaFuncAttributeMaxDynamicSharedMemorySize, SMEM_GEMM);

    const dim3 gemm_grid(HID / 128, NB / 128, 1);       // 8 x 64
    const dim3 head_grid(HID / 128, NB / 128, HEADS);   // 8 x 64 x 8

    // 0. fp16 weight copies
    cvt_fp16_kernel<<<(ENCK * HID / 4 + 255) / 256, 256>>>((const float4*)W_enc_in, (__half2*)wenc,   ENCK * HID / 4);
    cvt_fp16_kernel<<<(DECK * HID / 4 + 255) / 256, 256>>>((const float4*)W_dec_in, (__half2*)wdec,   DECK * HID / 4);
    cvt_fp16_kernel<<<(HID * HID / 4 + 255) / 256, 256>>>((const float4*)W_eh,      (__half2*)weh,    HID * HID / 4);
    cvt_fp16_kernel<<<(HEADS * HID * HID / 4 + 255) / 256, 256>>>((const float4*)W_heads, (__half2*)wheads, HEADS * HID * HID / 4);
    cvt_fp16_kernel<<<(HID * HID / 4 + 255) / 256, 256>>>((const float4*)W_dh,      (__half2*)wdh,    HID * HID / 4);
    cvt_fp16_kernel<<<(HID * HID / 4 + 255) / 256, 256>>>((const float4*)W1,        (__half2*)w1c,    HID * HID / 4);

    // 1. concat + fp16 inputs
    concat_kernel<<<(NB * (ENCK + DECK) + 255) / 256, 256>>>(s, a);

    // 2. enc_input = xenc @ W_enc_in + b_enc_in            (fp16 out)
    hgemm<false, true><<<gemm_grid, 256, SMEM_GEMM>>>(xenc, ENCK, wenc, 0, b_enc_in, 0, enc, 0, HID, ENCK);
    // 3. dec_input = adec @ W_dec_in + b_dec_in            (fp16 out)
    hgemm<false, true><<<gemm_grid, 256, SMEM_GEMM>>>(adec, DECK, wdec, 0, b_dec_in, 0, dec, 0, HID, DECK);
    // 4. encoder_h = relu(enc @ W_eh + b_eh)               (fp16 out)
    hgemm<true, true><<<gemm_grid, 256, SMEM_GEMM>>>(enc, HID, weh, 0, b_eh, 0, h, 0, HID, HID);
    // 5. decoder_H = relu(dec @ W_dh + b_dh)               (fp32 out)
    hgemm<true, false><<<gemm_grid, 256, SMEM_GEMM>>>(dec, HID, wdh, 0, b_dh, 0, dH, 0, HID, HID);
    // 6. encoder_heads[h] = relu(h @ W_heads[h] + b_heads[h])  (fp32 out)
    hgemm<true, false><<<head_grid, 256, SMEM_GEMM>>>(h, HID,
                                                      wheads, (size_t)HID * HID,
                                                      b_heads, (size_t)HID,
                                                      heads, (size_t)NB * HID,
                                                      HID, HID);
    // 7. scores + softmax
    scores_softmax_kernel<<<NB, 256>>>();
    // 8. context (fp16 out)
    context_kernel<<<(NB * HID / 4 + 255) / 256, 256>>>();
    // 9. x = relu(ctx @ W1 + b1)                           (fp32 out)
    hgemm<true, false><<<gemm_grid, 256, SMEM_GEMM>>>(ctx, HID, w1c, 0, b1, 0, x, 0, HID, HID);
    // 10. q = x @ W2 + b2
    final_dot_kernel<<<NB / 8, 256>>>(W2, b2, out);
}

// round 4
// speedup vs baseline: 5.8698x; 1.0506x over previous
#include <cuda_runtime.h>
#include <cuda_fp16.h>
#include <math.h>
#include <stdint.h>

// ---------------------------------------------------------------------------
// Problem constants
// ---------------------------------------------------------------------------
#define NB    8192      // batch
#define HID   1024
#define HEADS 8
#define ENCK  544       // 4*128 + 32
#define DECK  96
#define SDIM  512       // s columns
#define ADIM  128       // a columns
#define ACTN  32

// ---------------------------------------------------------------------------
// Scratch (device globals -- no runtime allocation allowed)
// ---------------------------------------------------------------------------
__device__ __align__(256) __half g_xenc [NB * ENCK];   // fp16(concat(s, a[:,:32]))
__device__ __align__(256) __half g_adec [NB * DECK];   // fp16(a[:, 32:])
__device__ __align__(256) __half g_enc  [NB * HID];    // enc_input (fp16)
__device__ __align__(256) __half g_dec  [NB * HID];    // dec_input (fp16)
__device__ __align__(256) __half g_h    [NB * HID];    // encoder_h (relu, fp16)
__device__ __align__(256) float  g_dH   [NB * HID];    // decoder_H (relu, fp32)
__device__ __align__(256) float  g_heads[HEADS * NB * HID]; // encoder_heads fp32
__device__ __align__(256) __half g_ctx  [NB * HID];    // context (fp16)
__device__ __align__(256) float  g_x    [NB * HID];    // relu(ctx@W1+b1) fp32

// fp16 weight copies
__device__ __align__(256) __half g_Wenc  [ENCK * HID];
__device__ __align__(256) __half g_Wdec  [DECK * HID];
__device__ __align__(256) __half g_Weh   [HID * HID];
__device__ __align__(256) __half g_Wheads[HEADS * HID * HID];
__device__ __align__(256) __half g_Wdh   [HID * HID];
__device__ __align__(256) __half g_W1    [HID * HID];

// ---------------------------------------------------------------------------
// Helpers
// ---------------------------------------------------------------------------
#define CP_ASYNC16(dst_u32, src_ptr) \
    asm volatile("cp.async.cg.shared.global [%0], [%1], 16;" \
                 :: "r"(dst_u32), "l"(src_ptr))
#define CP_COMMIT() asm volatile("cp.async.commit_group;")
#define CP_WAIT1()  asm volatile("cp.async.wait_group 1;")
#define CP_WAIT0()  asm volatile("cp.async.wait_group 0;")

// ---------------------------------------------------------------------------
// Elementwise fp32 -> fp16 copy (reads float4, writes 8B)
// ---------------------------------------------------------------------------
__global__ void cvt_fp16_kernel(const float4* __restrict__ src,
                                __half2* __restrict__ dst, int n4)
{
    int i = blockIdx.x * blockDim.x + threadIdx.x;
    if (i >= n4) return;
    float4 v = src[i];
    dst[2 * i]     = __floats2half2_rn(v.x, v.y);
    dst[2 * i + 1] = __floats2half2_rn(v.z, v.w);
}

// ---------------------------------------------------------------------------
// Concat + fp16 inputs
// ---------------------------------------------------------------------------
__global__ void concat_kernel(const float* __restrict__ s,
                              const float* __restrict__ a)
{
    int idx = blockIdx.x * blockDim.x + threadIdx.x;
    if (idx < NB * ENCK) {
        int b = idx / ENCK;
        int c = idx - b * ENCK;
        float v = (c < SDIM) ? s[(size_t)b * SDIM + c]
                             : a[(size_t)b * ADIM + (c - SDIM)];
        g_xenc[idx] = __float2half_rn(v);
    } else {
        int j = idx - NB * ENCK;
        if (j >= NB * DECK) return;
        int b = j / DECK;
        int c = j - b * DECK;
        g_adec[j] = __float2half_rn(a[(size_t)b * ADIM + ACTN + c]);
    }
}

// ---------------------------------------------------------------------------
// FP16 tensor-core GEMM: C[M,N] = act(A[M,K] @ W[K,N] + bias)
// 128x128 block tile, BK=32, double-buffered cp.async,
// 8 warps each computing 64x32 via m16n8k16 mma.sync.
// ---------------------------------------------------------------------------
#define AS_STRIDE 40     // halves per A smem row (32 + 8 pad)
#define BS_STRIDE 136    // halves per B smem row (128 + 8 pad)
#define AS_BUF    (128 * AS_STRIDE)   // 5120 halves
#define BS_BUF    (32 * BS_STRIDE)    // 4352 halves
#define SMEM_GEMM ((2 * AS_BUF + 2 * BS_BUF) * 2)  // 37888 bytes

template <bool RELU, bool HALF_OUT>
__global__ __launch_bounds__(256, 2)
void hgemm(const __half* __restrict__ A, int lda,
           const __half* __restrict__ W, size_t wstride,
           const float* __restrict__ bias, size_t bstride,
           void* __restrict__ Cv, size_t cstride,
           int N, int K)
{
    extern __shared__ __half smem[];

    const int tid    = threadIdx.x;
    const int lane   = tid & 31;
    const int wid    = tid >> 5;
    const int warp_m = wid >> 2;       // 0..1
    const int warp_n = wid & 3;        // 0..3
    const int bm = blockIdx.y * 128;
    const int bn = blockIdx.x * 128;
    const int z  = blockIdx.z;

    W    += (size_t)z * wstride;
    bias += (size_t)z * bstride;

    const uint32_t smem_u = (uint32_t)__cvta_generic_to_shared(smem);
    const uint32_t Bs_u   = smem_u + 2 * AS_BUF * 2;

    const __half* Ag = A + (size_t)bm * lda;
    const __half* Wg = W + bn;

    float acc[4][4][4];
#pragma unroll
    for (int mt = 0; mt < 4; ++mt)
#pragma unroll
        for (int nt = 0; nt < 4; ++nt)
#pragma unroll
            for (int r = 0; r < 4; ++r) acc[mt][nt][r] = 0.f;

    const int S = K >> 5;   // stages of 32

    auto load_stage = [&](int s, int buf) {
        const int k0 = s << 5;
        const uint32_t abase = smem_u + (uint32_t)buf * AS_BUF * 2;
        const uint32_t bbase = Bs_u   + (uint32_t)buf * BS_BUF * 2;
#pragma unroll
        for (int j = 0; j < 2; ++j) {                 // A: 128 x 32 halves
            int i = tid + 256 * j;
            int r = i >> 2, c = (i & 3) << 3;
            CP_ASYNC16(abase + (uint32_t)(r * AS_STRIDE + c) * 2,
                       Ag + (size_t)r * lda + k0 + c);
        }
#pragma unroll
        for (int j = 0; j < 2; ++j) {                 // B: 32 x 128 halves
            int i = tid + 256 * j;
            int r = i >> 4, c = (i & 15) << 3;
            CP_ASYNC16(bbase + (uint32_t)(r * BS_STRIDE + c) * 2,
                       Wg + (size_t)(k0 + r) * N + c);
        }
        CP_COMMIT();
    };

    load_stage(0, 0);

    const int a_row = lane & 15;
    const int a_col = (lane >> 4) << 3;
    const int b_row = lane & 15;

    for (int s = 0; s < S; ++s) {
        const int buf = s & 1;
        if (s + 1 < S) { load_stage(s + 1, buf ^ 1); CP_WAIT1(); }
        else           { CP_WAIT0(); }
        __syncthreads();

        const uint32_t abase = smem_u + (uint32_t)buf * AS_BUF * 2;
        const uint32_t bbase = Bs_u   + (uint32_t)buf * BS_BUF * 2;

#pragma unroll
        for (int ks = 0; ks < 2; ++ks) {
            uint32_t afr[4][4];
#pragma unroll
            for (int mt = 0; mt < 4; ++mt) {
                uint32_t addr = abase +
                    (uint32_t)((warp_m * 64 + mt * 16 + a_row) * AS_STRIDE
                               + ks * 16 + a_col) * 2;
                asm volatile(
                    "ldmatrix.sync.aligned.m8n8.x4.shared.b16 "
                    "{%0,%1,%2,%3}, [%4];"
                    : "=r"(afr[mt][0]), "=r"(afr[mt][1]),
                      "=r"(afr[mt][2]), "=r"(afr[mt][3])
                    : "r"(addr));
            }
            uint32_t bfr[4][2];
#pragma unroll
            for (int nt = 0; nt < 4; ++nt) {
                uint32_t addr = bbase +
                    (uint32_t)((ks * 16 + b_row) * BS_STRIDE
                               + warp_n * 32 + nt * 8) * 2;
                asm volatile(
                    "ldmatrix.sync.aligned.m8n8.x2.trans.shared.b16 "
                    "{%0,%1}, [%2];"
                    : "=r"(bfr[nt][0]), "=r"(bfr[nt][1])
                    : "r"(addr));
            }
#pragma unroll
            for (int mt = 0; mt < 4; ++mt)
#pragma unroll
                for (int nt = 0; nt < 4; ++nt) {
                    asm volatile(
                        "mma.sync.aligned.m16n8k16.row.col.f32.f16.f16.f32 "
                        "{%0,%1,%2,%3},{%4,%5,%6,%7},{%8,%9},{%0,%1,%2,%3};"
                        : "+f"(acc[mt][nt][0]), "+f"(acc[mt][nt][1]),
                          "+f"(acc[mt][nt][2]), "+f"(acc[mt][nt][3])
                        : "r"(afr[mt][0]), "r"(afr[mt][1]),
                          "r"(afr[mt][2]), "r"(afr[mt][3]),
                          "r"(bfr[nt][0]), "r"(bfr[nt][1]));
                }
        }
        __syncthreads();
    }

    // -- epilogue ----------------------------------------------------------
#pragma unroll
    for (int mt = 0; mt < 4; ++mt) {
        const int row0 = bm + warp_m * 64 + mt * 16 + (lane >> 2);
#pragma unroll
        for (int nt = 0; nt < 4; ++nt) {
            const int col = bn + warp_n * 32 + nt * 8 + 2 * (lane & 3);
            const float2 bv = *(const float2*)(bias + col);
            float2 v0, v1;
            v0.x = acc[mt][nt][0] + bv.x;
            v0.y = acc[mt][nt][1] + bv.y;
            v1.x = acc[mt][nt][2] + bv.x;
            v1.y = acc[mt][nt][3] + bv.y;
            if (RELU) {
                v0.x = fmaxf(v0.x, 0.f); v0.y = fmaxf(v0.y, 0.f);
                v1.x = fmaxf(v1.x, 0.f); v1.y = fmaxf(v1.y, 0.f);
            }
            if (HALF_OUT) {
                __half* C = (__half*)Cv + (size_t)z * cstride;
                *(__half2*)(C + (size_t)row0 * N + col)       = __floats2half2_rn(v0.x, v0.y);
                *(__half2*)(C + (size_t)(row0 + 8) * N + col) = __floats2half2_rn(v1.x, v1.y);
            } else {
                float* C = (float*)Cv + (size_t)z * cstride;
                *(float2*)(C + (size_t)row0 * N + col)       = v0;
                *(float2*)(C + (size_t)(row0 + 8) * N + col) = v1;
            }
        }
    }
}

// ---------------------------------------------------------------------------
// Fused attention: one block (256 thr) per batch row.
//   scores[h]  = dot(heads[h,b,:], dH[b,:])   (warp h; heads row staged to smem)
//   attn       = softmax(scores)
//   ctx[b,:]   = sum_h attn[h] * heads[h,b,:] (from smem) -> fp16
// Reads g_heads exactly ONCE from HBM.
// ---------------------------------------------------------------------------
__global__ __launch_bounds__(256)
void attn_fused_kernel()
{
    __shared__ float sh[HEADS * HID];       // 32 KB: staged head rows
    __shared__ float sattn[HEADS];

    const int b    = blockIdx.x;
    const int wid  = threadIdx.x >> 5;      // head index
    const int lane = threadIdx.x & 31;

    const float4* eh  = (const float4*)(g_heads + ((size_t)wid * NB + b) * HID);
    const float4* dH4 = (const float4*)(g_dH + (size_t)b * HID);
    float4* shw = (float4*)sh + wid * (HID / 4);

    float s = 0.f;
#pragma unroll 4
    for (int i = lane; i < HID / 4; i += 32) {
        float4 x = eh[i];
        float4 y = dH4[i];
        shw[i] = x;
        s += x.x * y.x + x.y * y.y + x.z * y.z + x.w * y.w;
    }
#pragma unroll
    for (int o = 16; o > 0; o >>= 1) s += __shfl_xor_sync(0xffffffffu, s, o);
    if (lane == 0) sattn[wid] = s;
    __syncthreads();

    if (threadIdx.x == 0) {
        float sc[HEADS];
#pragma unroll
        for (int h = 0; h < HEADS; ++h) sc[h] = sattn[h];
        float m = sc[0];
#pragma unroll
        for (int h = 1; h < HEADS; ++h) m = fmaxf(m, sc[h]);
        float e[HEADS], sum = 0.f;
#pragma unroll
        for (int h = 0; h < HEADS; ++h) { e[h] = __expf(sc[h] - m); sum += e[h]; }
        float inv = 1.f / sum;
#pragma unroll
        for (int h = 0; h < HEADS; ++h) sattn[h] = e[h] * inv;
    }
    __syncthreads();

    float w[HEADS];
#pragma unroll
    for (int h = 0; h < HEADS; ++h) w[h] = sattn[h];

    const int i = threadIdx.x;              // 256 threads x float4 = 1024 dims
    float4 acc = make_float4(0.f, 0.f, 0.f, 0.f);
#pragma unroll
    for (int h = 0; h < HEADS; ++h) {
        float4 v = ((const float4*)sh)[h * (HID / 4) + i];
        acc.x += v.x * w[h]; acc.y += v.y * w[h];
        acc.z += v.z * w[h]; acc.w += v.w * w[h];
    }
    __half2* dst = (__half2*)(g_ctx + (size_t)b * HID) + 2 * i;
    dst[0] = __floats2half2_rn(acc.x, acc.y);
    dst[1] = __floats2half2_rn(acc.z, acc.w);
}

// ---------------------------------------------------------------------------
// q[b] = dot(g_x[b,:], W2) + b2   -- one warp per row (fp32)
// ---------------------------------------------------------------------------
__global__ void final_dot_kernel(const float* __restrict__ W2,
                                 const float* __restrict__ b2,
                                 float* __restrict__ out)
{
    const int warp = (blockIdx.x * blockDim.x + threadIdx.x) >> 5;
    const int lane = threadIdx.x & 31;
    if (warp >= NB) return;

    const float4* xr = (const float4*)(g_x + (size_t)warp * HID);
    const float4* w4 = (const float4*)W2;
    float s = 0.f;
#pragma unroll 4
    for (int i = lane; i < HID / 4; i += 32) {
        float4 x = xr[i];
        float4 w = w4[i];
        s += x.x * w.x + x.y * w.y + x.z * w.z + x.w * w.w;
    }
#pragma unroll
    for (int o = 16; o > 0; o >>= 1) s += __shfl_xor_sync(0xffffffffu, s, o);
    if (lane == 0) out[warp] = s + b2[0];
}

// ---------------------------------------------------------------------------
// Launch
// ---------------------------------------------------------------------------
extern "C" void kernel_launch(void* const* d_in, const int* in_sizes, int n_in,
                              void* d_out, int out_size)
{
    const float* s        = (const float*)d_in[0];
    const float* a        = (const float*)d_in[1];
    const float* W_enc_in = (const float*)d_in[2];
    const float* b_enc_in = (const float*)d_in[3];
    const float* W_dec_in = (const float*)d_in[4];
    const float* b_dec_in = (const float*)d_in[5];
    const float* W_eh     = (const float*)d_in[6];
    const float* b_eh     = (const float*)d_in[7];
    const float* W_heads  = (const float*)d_in[8];
    const float* b_heads  = (const float*)d_in[9];
    const float* W_dh     = (const float*)d_in[10];
    const float* b_dh     = (const float*)d_in[11];
    const float* W1       = (const float*)d_in[12];
    const float* b1       = (const float*)d_in[13];
    const float* W2       = (const float*)d_in[14];
    const float* b2       = (const float*)d_in[15];
    float* out = (float*)d_out;

    __half *xenc, *adec, *enc, *dec, *h, *ctx;
    float *dH, *heads, *x;
    __half *wenc, *wdec, *weh, *wheads, *wdh, *w1c;
    cudaGetSymbolAddress((void**)&xenc,   g_xenc);
    cudaGetSymbolAddress((void**)&adec,   g_adec);
    cudaGetSymbolAddress((void**)&enc,    g_enc);
    cudaGetSymbolAddress((void**)&dec,    g_dec);
    cudaGetSymbolAddress((void**)&h,      g_h);
    cudaGetSymbolAddress((void**)&dH,     g_dH);
    cudaGetSymbolAddress((void**)&heads,  g_heads);
    cudaGetSymbolAddress((void**)&ctx,    g_ctx);
    cudaGetSymbolAddress((void**)&x,      g_x);
    cudaGetSymbolAddress((void**)&wenc,   g_Wenc);
    cudaGetSymbolAddress((void**)&wdec,   g_Wdec);
    cudaGetSymbolAddress((void**)&weh,    g_Weh);
    cudaGetSymbolAddress((void**)&wheads, g_Wheads);
    cudaGetSymbolAddress((void**)&wdh,    g_Wdh);
    cudaGetSymbolAddress((void**)&w1c,    g_W1);

    cudaFuncSetAttribute(hgemm<false, true>,
                         cudaFuncAttributeMaxDynamicSharedMemorySize, SMEM_GEMM);
    cudaFuncSetAttribute(hgemm<true, true>,
                         cudaFuncAttributeMaxDynamicSharedMemorySize, SMEM_GEMM);
    cudaFuncSetAttribute(hgemm<true, false>,
                         cudaFuncAttributeMaxDynamicSharedMemorySize, SMEM_GEMM);

    const dim3 gemm_grid(HID / 128, NB / 128, 1);       // 8 x 64
    const dim3 head_grid(HID / 128, NB / 128, HEADS);   // 8 x 64 x 8

    // 0. fp16 weight copies
    cvt_fp16_kernel<<<(ENCK * HID / 4 + 255) / 256, 256>>>((const float4*)W_enc_in, (__half2*)wenc,   ENCK * HID / 4);
    cvt_fp16_kernel<<<(DECK * HID / 4 + 255) / 256, 256>>>((const float4*)W_dec_in, (__half2*)wdec,   DECK * HID / 4);
    cvt_fp16_kernel<<<(HID * HID / 4 + 255) / 256, 256>>>((const float4*)W_eh,      (__half2*)weh,    HID * HID / 4);
    cvt_fp16_kernel<<<(HEADS * HID * HID / 4 + 255) / 256, 256>>>((const float4*)W_heads, (__half2*)wheads, HEADS * HID * HID / 4);
    cvt_fp16_kernel<<<(HID * HID / 4 + 255) / 256, 256>>>((const float4*)W_dh,      (__half2*)wdh,    HID * HID / 4);
    cvt_fp16_kernel<<<(HID * HID / 4 + 255) / 256, 256>>>((const float4*)W1,        (__half2*)w1c,    HID * HID / 4);

    // 1. concat + fp16 inputs
    concat_kernel<<<(NB * (ENCK + DECK) + 255) / 256, 256>>>(s, a);

    // 2. enc_input = xenc @ W_enc_in + b_enc_in            (fp16 out)
    hgemm<false, true><<<gemm_grid, 256, SMEM_GEMM>>>(xenc, ENCK, wenc, 0, b_enc_in, 0, enc, 0, HID, ENCK);
    // 3. dec_input = adec @ W_dec_in + b_dec_in            (fp16 out)
    hgemm<false, true><<<gemm_grid, 256, SMEM_GEMM>>>(adec, DECK, wdec, 0, b_dec_in, 0, dec, 0, HID, DECK);
    // 4. encoder_h = relu(enc @ W_eh + b_eh)               (fp16 out)
    hgemm<true, true><<<gemm_grid, 256, SMEM_GEMM>>>(enc, HID, weh, 0, b_eh, 0, h, 0, HID, HID);
    // 5. decoder_H = relu(dec @ W_dh + b_dh)               (fp32 out)
    hgemm<true, false><<<gemm_grid, 256, SMEM_GEMM>>>(dec, HID, wdh, 0, b_dh, 0, dH, 0, HID, HID);
    // 6. encoder_heads[h] = relu(h @ W_heads[h] + b_heads[h])  (fp32 out)
    hgemm<true, false><<<head_grid, 256, SMEM_GEMM>>>(h, HID,
                                                      wheads, (size_t)HID * HID,
                                                      b_heads, (size_t)HID,
                                                      heads, (size_t)NB * HID,
                                                      HID, HID);
    // 7. fused scores + softmax + context  (fp16 ctx out)
    attn_fused_kernel<<<NB, 256>>>();
    // 8. x = relu(ctx @ W1 + b1)                           (fp32 out)
    hgemm<true, false><<<gemm_grid, 256, SMEM_GEMM>>>(ctx, HID, w1c, 0, b1, 0, x, 0, HID, HID);
    // 9. q = x @ W2 + b2
    final_dot_kernel<<<NB / 8, 256>>>(W2, b2, out);
}

// round 6
// speedup vs baseline: 6.1416x; 1.0463x over previous
#include <cuda_runtime.h>
#include <cuda_fp16.h>
#include <math.h>
#include <stdint.h>

// ---------------------------------------------------------------------------
// Problem constants
// ---------------------------------------------------------------------------
#define NB    8192      // batch
#define HID   1024
#define HEADS 8
#define ENCK  544       // 4*128 + 32
#define DECK  96
#define SDIM  512       // s columns
#define ADIM  128       // a columns
#define ACTN  32

// ---------------------------------------------------------------------------
// Scratch (device globals -- no runtime allocation allowed)
// ---------------------------------------------------------------------------
__device__ __align__(256) __half g_xenc [NB * ENCK];   // fp16(concat(s, a[:,:32]))
__device__ __align__(256) __half g_adec [NB * DECK];   // fp16(a[:, 32:])
__device__ __align__(256) __half g_enc  [NB * HID];    // enc_input (fp16)
__device__ __align__(256) __half g_dec  [NB * HID];    // dec_input (fp16)
__device__ __align__(256) __half g_h    [NB * HID];    // encoder_h (relu, fp16)
__device__ __align__(256) __half g_dH   [NB * HID];    // decoder_H (relu, fp16)
__device__ __align__(256) __half g_heads[HEADS * NB * HID]; // encoder_heads fp16
__device__ __align__(256) __half g_ctx  [NB * HID];    // context (fp16)
__device__ __align__(256) float  g_x    [NB * HID];    // relu(ctx@W1+b1) fp32

// fp16 weight copies
__device__ __align__(256) __half g_Wenc  [ENCK * HID];
__device__ __align__(256) __half g_Wdec  [DECK * HID];
__device__ __align__(256) __half g_Weh   [HID * HID];
__device__ __align__(256) __half g_Wheads[HEADS * HID * HID];
__device__ __align__(256) __half g_Wdh   [HID * HID];
__device__ __align__(256) __half g_W1    [HID * HID];

// ---------------------------------------------------------------------------
// Helpers
// ---------------------------------------------------------------------------
#define CP_ASYNC16(dst_u32, src_ptr) \
    asm volatile("cp.async.cg.shared.global [%0], [%1], 16;" \
                 :: "r"(dst_u32), "l"(src_ptr))
#define CP_COMMIT() asm volatile("cp.async.commit_group;")
#define CP_WAIT1()  asm volatile("cp.async.wait_group 1;")
#define CP_WAIT0()  asm volatile("cp.async.wait_group 0;")

// ---------------------------------------------------------------------------
// Single merged fp32 -> fp16 weight conversion (all six weights)
// ---------------------------------------------------------------------------
#define N4_ENC  (ENCK * HID / 4)
#define N4_DEC  (DECK * HID / 4)
#define N4_SQ   (HID * HID / 4)
#define N4_HEAD (HEADS * HID * HID / 4)
#define N4_ALL  (N4_ENC + N4_DEC + 3 * N4_SQ + N4_HEAD)

__global__ void cvt_weights_kernel(const float4* __restrict__ Wenc,
                                   const float4* __restrict__ Wdec,
                                   const float4* __restrict__ Weh,
                                   const float4* __restrict__ Wheads,
                                   const float4* __restrict__ Wdh,
                                   const float4* __restrict__ W1)
{
    int i = blockIdx.x * blockDim.x + threadIdx.x;
    if (i >= N4_ALL) return;

    const float4* src;
    __half2* dst;
    int j = i;
    if (j < N4_ENC)                 { src = Wenc;   dst = (__half2*)g_Wenc; }
    else if ((j -= N4_ENC)  < N4_DEC)  { src = Wdec;   dst = (__half2*)g_Wdec; }
    else if ((j -= N4_DEC)  < N4_SQ)   { src = Weh;    dst = (__half2*)g_Weh; }
    else if ((j -= N4_SQ)   < N4_HEAD) { src = Wheads; dst = (__half2*)g_Wheads; }
    else if ((j -= N4_HEAD) < N4_SQ)   { src = Wdh;    dst = (__half2*)g_Wdh; }
    else    { j -= N4_SQ;                src = W1;     dst = (__half2*)g_W1; }

    float4 v = src[j];
    dst[2 * j]     = __floats2half2_rn(v.x, v.y);
    dst[2 * j + 1] = __floats2half2_rn(v.z, v.w);
}

// ---------------------------------------------------------------------------
// Concat + fp16 inputs
// ---------------------------------------------------------------------------
__global__ void concat_kernel(const float* __restrict__ s,
                              const float* __restrict__ a)
{
    int idx = blockIdx.x * blockDim.x + threadIdx.x;
    if (idx < NB * ENCK) {
        int b = idx / ENCK;
        int c = idx - b * ENCK;
        float v = (c < SDIM) ? s[(size_t)b * SDIM + c]
                             : a[(size_t)b * ADIM + (c - SDIM)];
        g_xenc[idx] = __float2half_rn(v);
    } else {
        int j = idx - NB * ENCK;
        if (j >= NB * DECK) return;
        int b = j / DECK;
        int c = j - b * DECK;
        g_adec[j] = __float2half_rn(a[(size_t)b * ADIM + ACTN + c]);
    }
}

// ---------------------------------------------------------------------------
// FP16 tensor-core GEMM: C[M,N] = act(A[M,K] @ W[K,N] + bias)
// 128x128 block tile, BK=32, double-buffered cp.async,
// 8 warps each computing 64x32 via m16n8k16 mma.sync.
// ---------------------------------------------------------------------------
#define AS_STRIDE 40     // halves per A smem row (32 + 8 pad)
#define BS_STRIDE 136    // halves per B smem row (128 + 8 pad)
#define AS_BUF    (128 * AS_STRIDE)   // 5120 halves
#define BS_BUF    (32 * BS_STRIDE)    // 4352 halves
#define SMEM_GEMM ((2 * AS_BUF + 2 * BS_BUF) * 2)  // 37888 bytes

template <bool RELU, bool HALF_OUT>
__global__ __launch_bounds__(256, 2)
void hgemm(const __half* __restrict__ A, int lda,
           const __half* __restrict__ W, size_t wstride,
           const float* __restrict__ bias, size_t bstride,
           void* __restrict__ Cv, size_t cstride,
           int N, int K)
{
    extern __shared__ __half smem[];

    const int tid    = threadIdx.x;
    const int lane   = tid & 31;
    const int wid    = tid >> 5;
    const int warp_m = wid >> 2;       // 0..1
    const int warp_n = wid & 3;        // 0..3
    const int bm = blockIdx.y * 128;
    const int bn = blockIdx.x * 128;
    const int z  = blockIdx.z;

    W    += (size_t)z * wstride;
    bias += (size_t)z * bstride;

    const uint32_t smem_u = (uint32_t)__cvta_generic_to_shared(smem);
    const uint32_t Bs_u   = smem_u + 2 * AS_BUF * 2;

    const __half* Ag = A + (size_t)bm * lda;
    const __half* Wg = W + bn;

    float acc[4][4][4];
#pragma unroll
    for (int mt = 0; mt < 4; ++mt)
#pragma unroll
        for (int nt = 0; nt < 4; ++nt)
#pragma unroll
            for (int r = 0; r < 4; ++r) acc[mt][nt][r] = 0.f;

    const int S = K >> 5;   // stages of 32

    auto load_stage = [&](int s, int buf) {
        const int k0 = s << 5;
        const uint32_t abase = smem_u + (uint32_t)buf * AS_BUF * 2;
        const uint32_t bbase = Bs_u   + (uint32_t)buf * BS_BUF * 2;
#pragma unroll
        for (int j = 0; j < 2; ++j) {                 // A: 128 x 32 halves
            int i = tid + 256 * j;
            int r = i >> 2, c = (i & 3) << 3;
            CP_ASYNC16(abase + (uint32_t)(r * AS_STRIDE + c) * 2,
                       Ag + (size_t)r * lda + k0 + c);
        }
#pragma unroll
        for (int j = 0; j < 2; ++j) {                 // B: 32 x 128 halves
            int i = tid + 256 * j;
            int r = i >> 4, c = (i & 15) << 3;
            CP_ASYNC16(bbase + (uint32_t)(r * BS_STRIDE + c) * 2,
                       Wg + (size_t)(k0 + r) * N + c);
        }
        CP_COMMIT();
    };

    load_stage(0, 0);

    const int a_row = lane & 15;
    const int a_col = (lane >> 4) << 3;
    const int b_row = lane & 15;

    for (int s = 0; s < S; ++s) {
        const int buf = s & 1;
        if (s + 1 < S) { load_stage(s + 1, buf ^ 1); CP_WAIT1(); }
        else           { CP_WAIT0(); }
        __syncthreads();

        const uint32_t abase = smem_u + (uint32_t)buf * AS_BUF * 2;
        const uint32_t bbase = Bs_u   + (uint32_t)buf * BS_BUF * 2;

#pragma unroll
        for (int ks = 0; ks < 2; ++ks) {
            uint32_t afr[4][4];
#pragma unroll
            for (int mt = 0; mt < 4; ++mt) {
                uint32_t addr = abase +
                    (uint32_t)((warp_m * 64 + mt * 16 + a_row) * AS_STRIDE
                               + ks * 16 + a_col) * 2;
                asm volatile(
                    "ldmatrix.sync.aligned.m8n8.x4.shared.b16 "
                    "{%0,%1,%2,%3}, [%4];"
                    : "=r"(afr[mt][0]), "=r"(afr[mt][1]),
                      "=r"(afr[mt][2]), "=r"(afr[mt][3])
                    : "r"(addr));
            }
            uint32_t bfr[4][2];
#pragma unroll
            for (int nt = 0; nt < 4; ++nt) {
                uint32_t addr = bbase +
                    (uint32_t)((ks * 16 + b_row) * BS_STRIDE
                               + warp_n * 32 + nt * 8) * 2;
                asm volatile(
                    "ldmatrix.sync.aligned.m8n8.x2.trans.shared.b16 "
                    "{%0,%1}, [%2];"
                    : "=r"(bfr[nt][0]), "=r"(bfr[nt][1])
                    : "r"(addr));
            }
#pragma unroll
            for (int mt = 0; mt < 4; ++mt)
#pragma unroll
                for (int nt = 0; nt < 4; ++nt) {
                    asm volatile(
                        "mma.sync.aligned.m16n8k16.row.col.f32.f16.f16.f32 "
                        "{%0,%1,%2,%3},{%4,%5,%6,%7},{%8,%9},{%0,%1,%2,%3};"
                        : "+f"(acc[mt][nt][0]), "+f"(acc[mt][nt][1]),
                          "+f"(acc[mt][nt][2]), "+f"(acc[mt][nt][3])
                        : "r"(afr[mt][0]), "r"(afr[mt][1]),
                          "r"(afr[mt][2]), "r"(afr[mt][3]),
                          "r"(bfr[nt][0]), "r"(bfr[nt][1]));
                }
        }
        __syncthreads();
    }

    // -- epilogue ----------------------------------------------------------
#pragma unroll
    for (int mt = 0; mt < 4; ++mt) {
        const int row0 = bm + warp_m * 64 + mt * 16 + (lane >> 2);
#pragma unroll
        for (int nt = 0; nt < 4; ++nt) {
            const int col = bn + warp_n * 32 + nt * 8 + 2 * (lane & 3);
            const float2 bv = *(const float2*)(bias + col);
            float2 v0, v1;
            v0.x = acc[mt][nt][0] + bv.x;
            v0.y = acc[mt][nt][1] + bv.y;
            v1.x = acc[mt][nt][2] + bv.x;
            v1.y = acc[mt][nt][3] + bv.y;
            if (RELU) {
                v0.x = fmaxf(v0.x, 0.f); v0.y = fmaxf(v0.y, 0.f);
                v1.x = fmaxf(v1.x, 0.f); v1.y = fmaxf(v1.y, 0.f);
            }
            if (HALF_OUT) {
                __half* C = (__half*)Cv + (size_t)z * cstride;
                *(__half2*)(C + (size_t)row0 * N + col)       = __floats2half2_rn(v0.x, v0.y);
                *(__half2*)(C + (size_t)(row0 + 8) * N + col) = __floats2half2_rn(v1.x, v1.y);
            } else {
                float* C = (float*)Cv + (size_t)z * cstride;
                *(float2*)(C + (size_t)row0 * N + col)       = v0;
                *(float2*)(C + (size_t)(row0 + 8) * N + col) = v1;
            }
        }
    }
}

// ---------------------------------------------------------------------------
// Fused attention: one block (256 thr) per batch row. fp16 heads/dH.
//   scores[h]  = dot(heads[h,b,:], dH[b,:])   (warp h; heads staged to smem)
//   attn       = softmax(scores)
//   ctx[b,:]   = sum_h attn[h] * heads[h,b,:] (from smem) -> fp16
// Reads g_heads exactly ONCE from HBM (128 MB fp16).
// ---------------------------------------------------------------------------
__global__ __launch_bounds__(256)
void attn_fused_kernel()
{
    __shared__ uint4 sh[HEADS * HID / 8];   // 16 KB fp16 heads rows
    __shared__ float sattn[HEADS];

    const int b    = blockIdx.x;
    const int wid  = threadIdx.x >> 5;      // head index
    const int lane = threadIdx.x & 31;

    const uint4* eh  = (const uint4*)(g_heads + ((size_t)wid * NB + b) * HID);
    const uint4* dH8 = (const uint4*)(g_dH + (size_t)b * HID);
    uint4* shw = sh + wid * (HID / 8);

    float s = 0.f;
#pragma unroll
    for (int i = lane; i < HID / 8; i += 32) {   // 4 iters
        uint4 x = eh[i];
        uint4 y = dH8[i];
        shw[i] = x;
        const __half2* xp = (const __half2*)&x;
        const __half2* yp = (const __half2*)&y;
#pragma unroll
        for (int j = 0; j < 4; ++j) {
            float2 fx = __half22float2(xp[j]);
            float2 fy = __half22float2(yp[j]);
            s += fx.x * fy.x + fx.y * fy.y;
        }
    }
#pragma unroll
    for (int o = 16; o > 0; o >>= 1) s += __shfl_xor_sync(0xffffffffu, s, o);
    if (lane == 0) sattn[wid] = s;
    __syncthreads();

    if (threadIdx.x == 0) {
        float sc[HEADS];
#pragma unroll
        for (int h = 0; h < HEADS; ++h) sc[h] = sattn[h];
        float m = sc[0];
#pragma unroll
        for (int h = 1; h < HEADS; ++h) m = fmaxf(m, sc[h]);
        float e[HEADS], sum = 0.f;
#pragma unroll
        for (int h = 0; h < HEADS; ++h) { e[h] = __expf(sc[h] - m); sum += e[h]; }
        float inv = 1.f / sum;
#pragma unroll
        for (int h = 0; h < HEADS; ++h) sattn[h] = e[h] * inv;
    }
    __syncthreads();

    float w[HEADS];
#pragma unroll
    for (int h = 0; h < HEADS; ++h) w[h] = sattn[h];

    // 256 threads x 4 dims = 1024; read staged fp16 heads from smem
    const int i = threadIdx.x;                    // half2 pair index
    const __half2* sh2 = (const __half2*)sh;
    float2 acc0 = make_float2(0.f, 0.f);
    float2 acc1 = make_float2(0.f, 0.f);
#pragma unroll
    for (int h = 0; h < HEADS; ++h) {
        float2 v0 = __half22float2(sh2[h * (HID / 2) + 2 * i]);
        float2 v1 = __half22float2(sh2[h * (HID / 2) + 2 * i + 1]);
        acc0.x += v0.x * w[h]; acc0.y += v0.y * w[h];
        acc1.x += v1.x * w[h]; acc1.y += v1.y * w[h];
    }
    __half2* dst = (__half2*)(g_ctx + (size_t)b * HID) + 2 * i;
    dst[0] = __floats2half2_rn(acc0.x, acc0.y);
    dst[1] = __floats2half2_rn(acc1.x, acc1.y);
}

// ---------------------------------------------------------------------------
// q[b] = dot(g_x[b,:], W2) + b2   -- one warp per row (fp32)
// ---------------------------------------------------------------------------
__global__ void final_dot_kernel(const float* __restrict__ W2,
                                 const float* __restrict__ b2,
                                 float* __restrict__ out)
{
    const int warp = (blockIdx.x * blockDim.x + threadIdx.x) >> 5;
    const int lane = threadIdx.x & 31;
    if (warp >= NB) return;

    const float4* xr = (const float4*)(g_x + (size_t)warp * HID);
    const float4* w4 = (const float4*)W2;
    float s = 0.f;
#pragma unroll 4
    for (int i = lane; i < HID / 4; i += 32) {
        float4 x = xr[i];
        float4 w = w4[i];
        s += x.x * w.x + x.y * w.y + x.z * w.z + x.w * w.w;
    }
#pragma unroll
    for (int o = 16; o > 0; o >>= 1) s += __shfl_xor_sync(0xffffffffu, s, o);
    if (lane == 0) out[warp] = s + b2[0];
}

// ---------------------------------------------------------------------------
// Launch
// ---------------------------------------------------------------------------
extern "C" void kernel_launch(void* const* d_in, const int* in_sizes, int n_in,
                              void* d_out, int out_size)
{
    const float* s        = (const float*)d_in[0];
    const float* a        = (const float*)d_in[1];
    const float* W_enc_in = (const float*)d_in[2];
    const float* b_enc_in = (const float*)d_in[3];
    const float* W_dec_in = (const float*)d_in[4];
    const float* b_dec_in = (const float*)d_in[5];
    const float* W_eh     = (const float*)d_in[6];
    const float* b_eh     = (const float*)d_in[7];
    const float* W_heads  = (const float*)d_in[8];
    const float* b_heads  = (const float*)d_in[9];
    const float* W_dh     = (const float*)d_in[10];
    const float* b_dh     = (const float*)d_in[11];
    const float* W1       = (const float*)d_in[12];
    const float* b1       = (const float*)d_in[13];
    const float* W2       = (const float*)d_in[14];
    const float* b2       = (const float*)d_in[15];
    float* out = (float*)d_out;

    __half *xenc, *adec, *enc, *dec, *h, *dH, *heads, *ctx;
    float *x;
    __half *wenc, *wdec, *weh, *wheads, *wdh, *w1c;
    cudaGetSymbolAddress((void**)&xenc,   g_xenc);
    cudaGetSymbolAddress((void**)&adec,   g_adec);
    cudaGetSymbolAddress((void**)&enc,    g_enc);
    cudaGetSymbolAddress((void**)&dec,    g_dec);
    cudaGetSymbolAddress((void**)&h,      g_h);
    cudaGetSymbolAddress((void**)&dH,     g_dH);
    cudaGetSymbolAddress((void**)&heads,  g_heads);
    cudaGetSymbolAddress((void**)&ctx,    g_ctx);
    cudaGetSymbolAddress((void**)&x,      g_x);
    cudaGetSymbolAddress((void**)&wenc,   g_Wenc);
    cudaGetSymbolAddress((void**)&wdec,   g_Wdec);
    cudaGetSymbolAddress((void**)&weh,    g_Weh);
    cudaGetSymbolAddress((void**)&wheads, g_Wheads);
    cudaGetSymbolAddress((void**)&wdh,    g_Wdh);
    cudaGetSymbolAddress((void**)&w1c,    g_W1);

    cudaFuncSetAttribute(hgemm<false, true>,
                         cudaFuncAttributeMaxDynamicSharedMemorySize, SMEM_GEMM);
    cudaFuncSetAttribute(hgemm<true, true>,
                         cudaFuncAttributeMaxDynamicSharedMemorySize, SMEM_GEMM);
    cudaFuncSetAttribute(hgemm<true, false>,
                         cudaFuncAttributeMaxDynamicSharedMemorySize, SMEM_GEMM);

    const dim3 gemm_grid(HID / 128, NB / 128, 1);       // 8 x 64
    const dim3 head_grid(HID / 128, NB / 128, HEADS);   // 8 x 64 x 8

    // 0. fp16 weight copies (single merged kernel)
    cvt_weights_kernel<<<(N4_ALL + 255) / 256, 256>>>(
        (const float4*)W_enc_in, (const float4*)W_dec_in, (const float4*)W_eh,
        (const float4*)W_heads, (const float4*)W_dh, (const float4*)W1);

    // 1. concat + fp16 inputs
    concat_kernel<<<(NB * (ENCK + DECK) + 255) / 256, 256>>>(s, a);

    // 2. enc_input = xenc @ W_enc_in + b_enc_in            (fp16 out)
    hgemm<false, true><<<gemm_grid, 256, SMEM_GEMM>>>(xenc, ENCK, wenc, 0, b_enc_in, 0, enc, 0, HID, ENCK);
    // 3. dec_input = adec @ W_dec_in + b_dec_in            (fp16 out)
    hgemm<false, true><<<gemm_grid, 256, SMEM_GEMM>>>(adec, DECK, wdec, 0, b_dec_in, 0, dec, 0, HID, DECK);
    // 4. encoder_h = relu(enc @ W_eh + b_eh)               (fp16 out)
    hgemm<true, true><<<gemm_grid, 256, SMEM_GEMM>>>(enc, HID, weh, 0, b_eh, 0, h, 0, HID, HID);
    // 5. decoder_H = relu(dec @ W_dh + b_dh)               (fp16 out)
    hgemm<true, true><<<gemm_grid, 256, SMEM_GEMM>>>(dec, HID, wdh, 0, b_dh, 0, dH, 0, HID, HID);
    // 6. encoder_heads[z] = relu(h @ W_heads[z] + b_heads[z])  (fp16 out)
    hgemm<true, true><<<head_grid, 256, SMEM_GEMM>>>(h, HID,
                                                     wheads, (size_t)HID * HID,
                                                     b_heads, (size_t)HID,
                                                     heads, (size_t)NB * HID,
                                                     HID, HID);
    // 7. fused scores + softmax + context  (fp16 ctx out)
    attn_fused_kernel<<<NB, 256>>>();
    // 8. x = relu(ctx @ W1 + b1)                           (fp32 out)
    hgemm<true, false><<<gemm_grid, 256, SMEM_GEMM>>>(ctx, HID, w1c, 0, b1, 0, x, 0, HID, HID);
    // 9. q = x @ W2 + b2
    final_dot_kernel<<<NB / 8, 256>>>(W2, b2, out);
}

// round 7
// speedup vs baseline: 7.3572x; 1.1979x over previous
#include <cuda_runtime.h>
#include <cuda_fp16.h>
#include <math.h>
#include <stdint.h>

// ---------------------------------------------------------------------------
// Problem constants
// ---------------------------------------------------------------------------
#define NB    8192      // batch
#define HID   1024
#define HEADS 8
#define ENCK  544       // 4*128 + 32
#define DECK  96
#define SDIM  512       // s columns
#define ADIM  128       // a columns
#define ACTN  32

// ---------------------------------------------------------------------------
// Scratch (device globals -- no runtime allocation allowed)
// ---------------------------------------------------------------------------
__device__ __align__(256) __half g_xenc [NB * ENCK];   // fp16(concat(s, a[:,:32]))
__device__ __align__(256) __half g_adec [NB * DECK];   // fp16(a[:, 32:])
__device__ __align__(256) __half g_enc  [NB * HID];    // enc_input (fp16)
__device__ __align__(256) __half g_dec  [NB * HID];    // dec_input (fp16)
__device__ __align__(256) __half g_h    [NB * HID];    // encoder_h (relu, fp16)
__device__ __align__(256) __half g_dH   [NB * HID];    // decoder_H (relu, fp16)
__device__ __align__(256) __half g_heads[HEADS * NB * HID]; // encoder_heads fp16
__device__ __align__(256) __half g_ctx  [NB * HID];    // context (fp16)
__device__ __align__(256) float  g_x    [NB * HID];    // relu(ctx@W1+b1) fp32

// fp16 weight copies
__device__ __align__(256) __half g_Wenc  [ENCK * HID];
__device__ __align__(256) __half g_Wdec  [DECK * HID];
__device__ __align__(256) __half g_Weh   [HID * HID];
__device__ __align__(256) __half g_Wheads[HEADS * HID * HID];
__device__ __align__(256) __half g_Wdh   [HID * HID];
__device__ __align__(256) __half g_W1    [HID * HID];

// ---------------------------------------------------------------------------
// Helpers
// ---------------------------------------------------------------------------
#define CP_ASYNC16(dst_u32, src_ptr) \
    asm volatile("cp.async.cg.shared.global [%0], [%1], 16;" \
                 :: "r"(dst_u32), "l"(src_ptr))
#define CP_COMMIT() asm volatile("cp.async.commit_group;")
#define CP_WAIT1()  asm volatile("cp.async.wait_group 1;")
#define CP_WAIT0()  asm volatile("cp.async.wait_group 0;")

// ---------------------------------------------------------------------------
// Single merged fp32 -> fp16 weight conversion (all six weights)
// ---------------------------------------------------------------------------
#define N4_ENC  (ENCK * HID / 4)
#define N4_DEC  (DECK * HID / 4)
#define N4_SQ   (HID * HID / 4)
#define N4_HEAD (HEADS * HID * HID / 4)
#define N4_ALL  (N4_ENC + N4_DEC + 3 * N4_SQ + N4_HEAD)

__global__ void cvt_weights_kernel(const float4* __restrict__ Wenc,
                                   const float4* __restrict__ Wdec,
                                   const float4* __restrict__ Weh,
                                   const float4* __restrict__ Wheads,
                                   const float4* __restrict__ Wdh,
                                   const float4* __restrict__ W1)
{
    int i = blockIdx.x * blockDim.x + threadIdx.x;
    if (i >= N4_ALL) return;

    const float4* src;
    __half2* dst;
    int j = i;
    if (j < N4_ENC)                 { src = Wenc;   dst = (__half2*)g_Wenc; }
    else if ((j -= N4_ENC)  < N4_DEC)  { src = Wdec;   dst = (__half2*)g_Wdec; }
    else if ((j -= N4_DEC)  < N4_SQ)   { src = Weh;    dst = (__half2*)g_Weh; }
    else if ((j -= N4_SQ)   < N4_HEAD) { src = Wheads; dst = (__half2*)g_Wheads; }
    else if ((j -= N4_HEAD) < N4_SQ)   { src = Wdh;    dst = (__half2*)g_Wdh; }
    else    { j -= N4_SQ;                src = W1;     dst = (__half2*)g_W1; }

    float4 v = src[j];
    dst[2 * j]     = __floats2half2_rn(v.x, v.y);
    dst[2 * j + 1] = __floats2half2_rn(v.z, v.w);
}

// ---------------------------------------------------------------------------
// Concat + fp16 inputs
// ---------------------------------------------------------------------------
__global__ void concat_kernel(const float* __restrict__ s,
                              const float* __restrict__ a)
{
    int idx = blockIdx.x * blockDim.x + threadIdx.x;
    if (idx < NB * ENCK) {
        int b = idx / ENCK;
        int c = idx - b * ENCK;
        float v = (c < SDIM) ? s[(size_t)b * SDIM + c]
                             : a[(size_t)b * ADIM + (c - SDIM)];
        g_xenc[idx] = __float2half_rn(v);
    } else {
        int j = idx - NB * ENCK;
        if (j >= NB * DECK) return;
        int b = j / DECK;
        int c = j - b * DECK;
        g_adec[j] = __float2half_rn(a[(size_t)b * ADIM + ACTN + c]);
    }
}

// ---------------------------------------------------------------------------
// FP16 tensor-core GEMM: C[M,N] = act(A[M,K] @ W[K,N] + bias)
// 128x128 block tile, BK=32, THREE-stage cp.async pipeline (one barrier per
// K-chunk), 8 warps each computing 64x32 via m16n8k16 mma.sync.
// ---------------------------------------------------------------------------
#define AS_STRIDE 40     // halves per A smem row (32 + 8 pad)
#define BS_STRIDE 136    // halves per B smem row (128 + 8 pad)
#define AS_BUF    (128 * AS_STRIDE)   // 5120 halves
#define BS_BUF    (32 * BS_STRIDE)    // 4352 halves
#define NSTAGE    3
#define SMEM_GEMM ((NSTAGE * AS_BUF + NSTAGE * BS_BUF) * 2)  // 56832 bytes

template <bool RELU, bool HALF_OUT>
__global__ __launch_bounds__(256, 2)
void hgemm(const __half* __restrict__ A, int lda,
           const __half* __restrict__ W, size_t wstride,
           const float* __restrict__ bias, size_t bstride,
           void* __restrict__ Cv, size_t cstride,
           int N, int K)
{
    extern __shared__ __half smem[];

    const int tid    = threadIdx.x;
    const int lane   = tid & 31;
    const int wid    = tid >> 5;
    const int warp_m = wid >> 2;       // 0..1
    const int warp_n = wid & 3;        // 0..3
    const int bm = blockIdx.y * 128;
    const int bn = blockIdx.x * 128;
    const int z  = blockIdx.z;

    W    += (size_t)z * wstride;
    bias += (size_t)z * bstride;

    const uint32_t smem_u = (uint32_t)__cvta_generic_to_shared(smem);
    const uint32_t Bs_u   = smem_u + NSTAGE * AS_BUF * 2;

    const __half* Ag = A + (size_t)bm * lda;
    const __half* Wg = W + bn;

    float acc[4][4][4];
#pragma unroll
    for (int mt = 0; mt < 4; ++mt)
#pragma unroll
        for (int nt = 0; nt < 4; ++nt)
#pragma unroll
            for (int r = 0; r < 4; ++r) acc[mt][nt][r] = 0.f;

    const int S = K >> 5;   // stages of 32 (min here is 3)

    auto load_stage = [&](int s, int buf) {
        const int k0 = s << 5;
        const uint32_t abase = smem_u + (uint32_t)buf * AS_BUF * 2;
        const uint32_t bbase = Bs_u   + (uint32_t)buf * BS_BUF * 2;
#pragma unroll
        for (int j = 0; j < 2; ++j) {                 // A: 128 x 32 halves
            int i = tid + 256 * j;
            int r = i >> 2, c = (i & 3) << 3;
            CP_ASYNC16(abase + (uint32_t)(r * AS_STRIDE + c) * 2,
                       Ag + (size_t)r * lda + k0 + c);
        }
#pragma unroll
        for (int j = 0; j < 2; ++j) {                 // B: 32 x 128 halves
            int i = tid + 256 * j;
            int r = i >> 4, c = (i & 15) << 3;
            CP_ASYNC16(bbase + (uint32_t)(r * BS_STRIDE + c) * 2,
                       Wg + (size_t)(k0 + r) * N + c);
        }
        CP_COMMIT();
    };

    load_stage(0, 0);
    load_stage(1, 1);

    // ldmatrix lane geometry
    const int a_row  = lane & 15;
    const int a_col  = (lane >> 4) << 3;
    // B x4-trans: lane L -> row (L&7)+((L>>3)&1)*8, col-pair select L>>4
    const int b_row4 = (lane & 7) + ((lane >> 3) & 1) * 8;
    const int b_csel = (lane >> 4);        // 0 or 1 -> nt, nt+1

    int buf = 0;
    for (int s = 0; s < S; ++s) {
        if (s + 1 < S) CP_WAIT1();
        else           CP_WAIT0();
        __syncthreads();

        if (s + 2 < S) {
            int nb = buf + 2; if (nb >= NSTAGE) nb -= NSTAGE;
            load_stage(s + 2, nb);
        }

        const uint32_t abase = smem_u + (uint32_t)buf * AS_BUF * 2;
        const uint32_t bbase = Bs_u   + (uint32_t)buf * BS_BUF * 2;

#pragma unroll
        for (int ks = 0; ks < 2; ++ks) {
            uint32_t afr[4][4];
#pragma unroll
            for (int mt = 0; mt < 4; ++mt) {
                uint32_t addr = abase +
                    (uint32_t)((warp_m * 64 + mt * 16 + a_row) * AS_STRIDE
                               + ks * 16 + a_col) * 2;
                asm volatile(
                    "ldmatrix.sync.aligned.m8n8.x4.shared.b16 "
                    "{%0,%1,%2,%3}, [%4];"
                    : "=r"(afr[mt][0]), "=r"(afr[mt][1]),
                      "=r"(afr[mt][2]), "=r"(afr[mt][3])
                    : "r"(addr));
            }
            uint32_t bfr[4][2];
#pragma unroll
            for (int np = 0; np < 2; ++np) {          // nt pairs {0,1},{2,3}
                int nt = np * 2;
                uint32_t addr = bbase +
                    (uint32_t)((ks * 16 + b_row4) * BS_STRIDE
                               + warp_n * 32 + (nt + b_csel) * 8) * 2;
                asm volatile(
                    "ldmatrix.sync.aligned.m8n8.x4.trans.shared.b16 "
                    "{%0,%1,%2,%3}, [%4];"
                    : "=r"(bfr[nt][0]), "=r"(bfr[nt][1]),
                      "=r"(bfr[nt + 1][0]), "=r"(bfr[nt + 1][1])
                    : "r"(addr));
            }
#pragma unroll
            for (int mt = 0; mt < 4; ++mt)
#pragma unroll
                for (int nt = 0; nt < 4; ++nt) {
                    asm volatile(
                        "mma.sync.aligned.m16n8k16.row.col.f32.f16.f16.f32 "
                        "{%0,%1,%2,%3},{%4,%5,%6,%7},{%8,%9},{%0,%1,%2,%3};"
                        : "+f"(acc[mt][nt][0]), "+f"(acc[mt][nt][1]),
                          "+f"(acc[mt][nt][2]), "+f"(acc[mt][nt][3])
                        : "r"(afr[mt][0]), "r"(afr[mt][1]),
                          "r"(afr[mt][2]), "r"(afr[mt][3]),
                          "r"(bfr[nt][0]), "r"(bfr[nt][1]));
                }
        }
        if (++buf >= NSTAGE) buf = 0;
    }

    // -- epilogue ----------------------------------------------------------
#pragma unroll
    for (int mt = 0; mt < 4; ++mt) {
        const int row0 = bm + warp_m * 64 + mt * 16 + (lane >> 2);
#pragma unroll
        for (int nt = 0; nt < 4; ++nt) {
            const int col = bn + warp_n * 32 + nt * 8 + 2 * (lane & 3);
            const float2 bv = *(const float2*)(bias + col);
            float2 v0, v1;
            v0.x = acc[mt][nt][0] + bv.x;
            v0.y = acc[mt][nt][1] + bv.y;
            v1.x = acc[mt][nt][2] + bv.x;
            v1.y = acc[mt][nt][3] + bv.y;
            if (RELU) {
                v0.x = fmaxf(v0.x, 0.f); v0.y = fmaxf(v0.y, 0.f);
                v1.x = fmaxf(v1.x, 0.f); v1.y = fmaxf(v1.y, 0.f);
            }
            if (HALF_OUT) {
                __half* C = (__half*)Cv + (size_t)z * cstride;
                *(__half2*)(C + (size_t)row0 * N + col)       = __floats2half2_rn(v0.x, v0.y);
                *(__half2*)(C + (size_t)(row0 + 8) * N + col) = __floats2half2_rn(v1.x, v1.y);
            } else {
                float* C = (float*)Cv + (size_t)z * cstride;
                *(float2*)(C + (size_t)row0 * N + col)       = v0;
                *(float2*)(C + (size_t)(row0 + 8) * N + col) = v1;
            }
        }
    }
}

// ---------------------------------------------------------------------------
// Fused attention: one block (256 thr) per batch row. fp16 heads/dH.
// ---------------------------------------------------------------------------
__global__ __launch_bounds__(256)
void attn_fused_kernel()
{
    __shared__ uint4 sh[HEADS * HID / 8];   // 16 KB fp16 heads rows
    __shared__ float sattn[HEADS];

    const int b    = blockIdx.x;
    const int wid  = threadIdx.x >> 5;      // head index
    const int lane = threadIdx.x & 31;

    const uint4* eh  = (const uint4*)(g_heads + ((size_t)wid * NB + b) * HID);
    const uint4* dH8 = (const uint4*)(g_dH + (size_t)b * HID);
    uint4* shw = sh + wid * (HID / 8);

    float s = 0.f;
#pragma unroll
    for (int i = lane; i < HID / 8; i += 32) {   // 4 iters
        uint4 x = eh[i];
        uint4 y = dH8[i];
        shw[i] = x;
        const __half2* xp = (const __half2*)&x;
        const __half2* yp = (const __half2*)&y;
#pragma unroll
        for (int j = 0; j < 4; ++j) {
            float2 fx = __half22float2(xp[j]);
            float2 fy = __half22float2(yp[j]);
            s += fx.x * fy.x + fx.y * fy.y;
        }
    }
#pragma unroll
    for (int o = 16; o > 0; o >>= 1) s += __shfl_xor_sync(0xffffffffu, s, o);
    if (lane == 0) sattn[wid] = s;
    __syncthreads();

    if (threadIdx.x == 0) {
        float sc[HEADS];
#pragma unroll
        for (int h = 0; h < HEADS; ++h) sc[h] = sattn[h];
        float m = sc[0];
#pragma unroll
        for (int h = 1; h < HEADS; ++h) m = fmaxf(m, sc[h]);
        float e[HEADS], sum = 0.f;
#pragma unroll
        for (int h = 0; h < HEADS; ++h) { e[h] = __expf(sc[h] - m); sum += e[h]; }
        float inv = 1.f / sum;
#pragma unroll
        for (int h = 0; h < HEADS; ++h) sattn[h] = e[h] * inv;
    }
    __syncthreads();

    float w[HEADS];
#pragma unroll
    for (int h = 0; h < HEADS; ++h) w[h] = sattn[h];

    const int i = threadIdx.x;                    // half2 pair index
    const __half2* sh2 = (const __half2*)sh;
    float2 acc0 = make_float2(0.f, 0.f);
    float2 acc1 = make_float2(0.f, 0.f);
#pragma unroll
    for (int h = 0; h < HEADS; ++h) {
        float2 v0 = __half22float2(sh2[h * (HID / 2) + 2 * i]);
        float2 v1 = __half22float2(sh2[h * (HID / 2) + 2 * i + 1]);
        acc0.x += v0.x * w[h]; acc0.y += v0.y * w[h];
        acc1.x += v1.x * w[h]; acc1.y += v1.y * w[h];
    }
    __half2* dst = (__half2*)(g_ctx + (size_t)b * HID) + 2 * i;
    dst[0] = __floats2half2_rn(acc0.x, acc0.y);
    dst[1] = __floats2half2_rn(acc1.x, acc1.y);
}

// ---------------------------------------------------------------------------
// q[b] = dot(g_x[b,:], W2) + b2   -- one warp per row (fp32)
// ---------------------------------------------------------------------------
__global__ void final_dot_kernel(const float* __restrict__ W2,
                                 const float* __restrict__ b2,
                                 float* __restrict__ out)
{
    const int warp = (blockIdx.x * blockDim.x + threadIdx.x) >> 5;
    const int lane = threadIdx.x & 31;
    if (warp >= NB) return;

    const float4* xr = (const float4*)(g_x + (size_t)warp * HID);
    const float4* w4 = (const float4*)W2;
    float s = 0.f;
#pragma unroll 4
    for (int i = lane; i < HID / 4; i += 32) {
        float4 x = xr[i];
        float4 w = w4[i];
        s += x.x * w.x + x.y * w.y + x.z * w.z + x.w * w.w;
    }
#pragma unroll
    for (int o = 16; o > 0; o >>= 1) s += __shfl_xor_sync(0xffffffffu, s, o);
    if (lane == 0) out[warp] = s + b2[0];
}

// ---------------------------------------------------------------------------
// Launch
// ---------------------------------------------------------------------------
extern "C" void kernel_launch(void* const* d_in, const int* in_sizes, int n_in,
                              void* d_out, int out_size)
{
    const float* s        = (const float*)d_in[0];
    const float* a        = (const float*)d_in[1];
    const float* W_enc_in = (const float*)d_in[2];
    const float* b_enc_in = (const float*)d_in[3];
    const float* W_dec_in = (const float*)d_in[4];
    const float* b_dec_in = (const float*)d_in[5];
    const float* W_eh     = (const float*)d_in[6];
    const float* b_eh     = (const float*)d_in[7];
    const float* W_heads  = (const float*)d_in[8];
    const float* b_heads  = (const float*)d_in[9];
    const float* W_dh     = (const float*)d_in[10];
    const float* b_dh     = (const float*)d_in[11];
    const float* W1       = (const float*)d_in[12];
    const float* b1       = (const float*)d_in[13];
    const float* W2       = (const float*)d_in[14];
    const float* b2       = (const float*)d_in[15];
    float* out = (float*)d_out;

    __half *xenc, *adec, *enc, *dec, *h, *dH, *heads, *ctx;
    float *x;
    __half *wenc, *wdec, *weh, *wheads, *wdh, *w1c;
    cudaGetSymbolAddress((void**)&xenc,   g_xenc);
    cudaGetSymbolAddress((void**)&adec,   g_adec);
    cudaGetSymbolAddress((void**)&enc,    g_enc);
    cudaGetSymbolAddress((void**)&dec,    g_dec);
    cudaGetSymbolAddress((void**)&h,      g_h);
    cudaGetSymbolAddress((void**)&dH,     g_dH);
    cudaGetSymbolAddress((void**)&heads,  g_heads);
    cudaGetSymbolAddress((void**)&ctx,    g_ctx);
    cudaGetSymbolAddress((void**)&x,      g_x);
    cudaGetSymbolAddress((void**)&wenc,   g_Wenc);
    cudaGetSymbolAddress((void**)&wdec,   g_Wdec);
    cudaGetSymbolAddress((void**)&weh,    g_Weh);
    cudaGetSymbolAddress((void**)&wheads, g_Wheads);
    cudaGetSymbolAddress((void**)&wdh,    g_Wdh);
    cudaGetSymbolAddress((void**)&w1c,    g_W1);

    cudaFuncSetAttribute(hgemm<false, true>,
                         cudaFuncAttributeMaxDynamicSharedMemorySize, SMEM_GEMM);
    cudaFuncSetAttribute(hgemm<true, true>,
                         cudaFuncAttributeMaxDynamicSharedMemorySize, SMEM_GEMM);
    cudaFuncSetAttribute(hgemm<true, false>,
                         cudaFuncAttributeMaxDynamicSharedMemorySize, SMEM_GEMM);

    const dim3 gemm_grid(HID / 128, NB / 128, 1);       // 8 x 64
    const dim3 head_grid(HID / 128, NB / 128, HEADS);   // 8 x 64 x 8

    // 0. fp16 weight copies (single merged kernel)
    cvt_weights_kernel<<<(N4_ALL + 255) / 256, 256>>>(
        (const float4*)W_enc_in, (const float4*)W_dec_in, (const float4*)W_eh,
        (const float4*)W_heads, (const float4*)W_dh, (const float4*)W1);

    // 1. concat + fp16 inputs
    concat_kernel<<<(NB * (ENCK + DECK) + 255) / 256, 256>>>(s, a);

    // 2. enc_input = xenc @ W_enc_in + b_enc_in            (fp16 out)
    hgemm<false, true><<<gemm_grid, 256, SMEM_GEMM>>>(xenc, ENCK, wenc, 0, b_enc_in, 0, enc, 0, HID, ENCK);
    // 3. dec_input = adec @ W_dec_in + b_dec_in            (fp16 out)
    hgemm<false, true><<<gemm_grid, 256, SMEM_GEMM>>>(adec, DECK, wdec, 0, b_dec_in, 0, dec, 0, HID, DECK);
    // 4. encoder_h = relu(enc @ W_eh + b_eh)               (fp16 out)
    hgemm<true, true><<<gemm_grid, 256, SMEM_GEMM>>>(enc, HID, weh, 0, b_eh, 0, h, 0, HID, HID);
    // 5. decoder_H = relu(dec @ W_dh + b_dh)               (fp16 out)
    hgemm<true, true><<<gemm_grid, 256, SMEM_GEMM>>>(dec, HID, wdh, 0, b_dh, 0, dH, 0, HID, HID);
    // 6. encoder_heads[z] = relu(h @ W_heads[z] + b_heads[z])  (fp16 out)
    hgemm<true, true><<<head_grid, 256, SMEM_GEMM>>>(h, HID,
                                                     wheads, (size_t)HID * HID,
                                                     b_heads, (size_t)HID,
                                                     heads, (size_t)NB * HID,
                                                     HID, HID);
    // 7. fused scores + softmax + context  (fp16 ctx out)
    attn_fused_kernel<<<NB, 256>>>();
    // 8. x = relu(ctx @ W1 + b1)                           (fp32 out)
    hgemm<true, false><<<gemm_grid, 256, SMEM_GEMM>>>(ctx, HID, w1c, 0, b1, 0, x, 0, HID, HID);
    // 9. q = x @ W2 + b2
    final_dot_kernel<<<NB / 8, 256>>>(W2, b2, out);
}